// round 11
// baseline (speedup 1.0000x reference)
#include <cuda_runtime.h>
#include <cuda_bf16.h>
#include <math.h>
#include <stdint.h>

#define BATCH    2
#define SEQ      1024
#define DIMM     1024
#define D_STATE  64
#define D_CONV   4
#define N_HEADS  8
#define D_INNER  2048
#define HEAD_DIM 256
#define D_IN_PROJ 4232          // 2048 + 2048 + 8 + 64 + 64
#define ML       (BATCH*SEQ)    // 2048
#define NSEG     8
#define SEG_LEN  128            // SEQ / NSEG

// ---------------- scratch (device globals: allocation-free) ----------------
__device__ float g_zx[(size_t)ML * D_IN_PROJ];      // in_proj output
__device__ float g_xconv[(size_t)ML * D_INNER];     // silu(conv(xc)) == xh
__device__ float g_abar[ML * N_HEADS];
__device__ float g_aseg[BATCH * N_HEADS * NSEG];    // per-segment decay product
__device__ float g_state[(size_t)BATCH * N_HEADS * NSEG * HEAD_DIM * D_STATE]; // 8MB
__device__ float g_sumsq[ML];                        // per-row sum of y^2

// bf16 hi/lo split buffers
__device__ __nv_bfloat16 g_xhi[(size_t)ML * DIMM];
__device__ __nv_bfloat16 g_xlo[(size_t)ML * DIMM];
__device__ __nv_bfloat16 g_w1hi[(size_t)D_IN_PROJ * DIMM];
__device__ __nv_bfloat16 g_w1lo[(size_t)D_IN_PROJ * DIMM];
__device__ __nv_bfloat16 g_yhi[(size_t)ML * D_INNER];
__device__ __nv_bfloat16 g_ylo[(size_t)ML * D_INNER];
__device__ __nv_bfloat16 g_w2hi[(size_t)DIMM * D_INNER];
__device__ __nv_bfloat16 g_w2lo[(size_t)DIMM * D_INNER];

// ---------------- PTX helpers (sm_80-era, compute_103-safe) ----------------
__device__ __forceinline__ uint32_t smem_u32(const void* p) {
    uint32_t a;
    asm("{ .reg .u64 t; cvta.to.shared.u64 t, %1; cvt.u32.u64 %0, t; }"
        : "=r"(a) : "l"(p));
    return a;
}
__device__ __forceinline__ void cp_async16(uint32_t saddr, const void* gaddr, uint32_t srcsz) {
    asm volatile("cp.async.cg.shared.global [%0], [%1], 16, %2;"
                 :: "r"(saddr), "l"(gaddr), "r"(srcsz) : "memory");
}
__device__ __forceinline__ void cp_commit() {
    asm volatile("cp.async.commit_group;" ::: "memory");
}
__device__ __forceinline__ void cp_wait2() {
    asm volatile("cp.async.wait_group 2;" ::: "memory");
}
__device__ __forceinline__ void ldsm_x4(uint32_t* r, uint32_t addr) {
    asm volatile("ldmatrix.sync.aligned.m8n8.x4.shared.b16 {%0,%1,%2,%3}, [%4];"
                 : "=r"(r[0]), "=r"(r[1]), "=r"(r[2]), "=r"(r[3]) : "r"(addr));
}
__device__ __forceinline__ void mma16816(float* c, const uint32_t* a, const uint32_t* b) {
    asm volatile(
        "mma.sync.aligned.m16n8k16.row.col.f32.bf16.bf16.f32 "
        "{%0,%1,%2,%3}, {%4,%5,%6,%7}, {%8,%9}, {%0,%1,%2,%3};"
        : "+f"(c[0]), "+f"(c[1]), "+f"(c[2]), "+f"(c[3])
        : "r"(a[0]), "r"(a[1]), "r"(a[2]), "r"(a[3]), "r"(b[0]), "r"(b[1]));
}

// ---------------- fused fp32 -> bf16 hi/lo split for x, w1, w2 --------------
#define N4X  (ML * DIMM / 4)            // 524288
#define N4W1 (D_IN_PROJ * DIMM / 4)     // 1083392
#define N4W2 (DIMM * D_INNER / 4)       // 524288
__global__ __launch_bounds__(256) void split_all(
    const float* __restrict__ x, const float* __restrict__ w1,
    const float* __restrict__ w2)
{
    int i = blockIdx.x * 256 + threadIdx.x;
    const float* s;
    __nv_bfloat16 *hi, *lo;
    int j;
    if (i < N4X) { s = x; hi = g_xhi; lo = g_xlo; j = i; }
    else if (i < N4X + N4W1) { s = w1; hi = g_w1hi; lo = g_w1lo; j = i - N4X; }
    else if (i < N4X + N4W1 + N4W2) { s = w2; hi = g_w2hi; lo = g_w2lo; j = i - N4X - N4W1; }
    else return;

    float4 v = reinterpret_cast<const float4*>(s)[j];
    __nv_bfloat16 h0 = __float2bfloat16(v.x);
    __nv_bfloat16 h1 = __float2bfloat16(v.y);
    __nv_bfloat16 h2 = __float2bfloat16(v.z);
    __nv_bfloat16 h3 = __float2bfloat16(v.w);
    __nv_bfloat16 l0 = __float2bfloat16(v.x - __bfloat162float(h0));
    __nv_bfloat16 l1 = __float2bfloat16(v.y - __bfloat162float(h1));
    __nv_bfloat16 l2 = __float2bfloat16(v.z - __bfloat162float(h2));
    __nv_bfloat16 l3 = __float2bfloat16(v.w - __bfloat162float(h3));
    __nv_bfloat162 hh0{h0, h1}, hh1{h2, h3}, ll0{l0, l1}, ll1{l2, l3};
    reinterpret_cast<__nv_bfloat162*>(hi)[j * 2 + 0] = hh0;
    reinterpret_cast<__nv_bfloat162*>(hi)[j * 2 + 1] = hh1;
    reinterpret_cast<__nv_bfloat162*>(lo)[j * 2 + 0] = ll0;
    reinterpret_cast<__nv_bfloat162*>(lo)[j * 2 + 1] = ll1;
}

// ---------------- mma.sync GEMM (bf16x3, 3-stage, 512 threads) --------------
// CTA: 128x128 tile, BK=64, 512 threads = 16 warps (2M x 8N), warp tile 64x16.
// 4 warps/SMSP to hide ldsm + HMMA latency; smem 192KB (3 stages), 1 CTA/SM.
#define TSZ 16384
__global__ __launch_bounds__(512, 1) void gemm_mma(
    const __nv_bfloat16* __restrict__ Ahi, const __nv_bfloat16* __restrict__ Alo,
    const __nv_bfloat16* __restrict__ Bhi, const __nv_bfloat16* __restrict__ Blo,
    float* __restrict__ C, int M, int N, int K,
    const float* __restrict__ row_sumsq)
{
    extern __shared__ char smem[];
    const int tid  = threadIdx.x;
    const int wid  = tid >> 5;
    const int lane = tid & 31;
    const int bm = blockIdx.y * 128, bn = blockIdx.x * 128;
    const int wm = (wid >> 3) * 64;       // 2 M groups
    const int wn = (wid & 7) * 16;        // 8 N groups of 16

    const uint32_t sbase = smem_u32(smem);

    float acc[4][2][4];
#pragma unroll
    for (int mi = 0; mi < 4; mi++)
#pragma unroll
        for (int ni = 0; ni < 2; ni++)
#pragma unroll
            for (int v = 0; v < 4; v++) acc[mi][ni][v] = 0.f;

    const int NC = K >> 6;

    auto load_stage = [&](int buf, int k0) {
        uint32_t st = sbase + buf * 4 * TSZ;
#pragma unroll
        for (int it = 0; it < 2; it++) {
            int cid = it * 512 + tid;
            int r = cid >> 3, j = cid & 7;
            uint32_t swz = (uint32_t)((r * 8 + (j ^ (r & 7))) * 16);
            size_t aoff = (size_t)(bm + r) * K + k0 + j * 8;
            cp_async16(st + swz,           Ahi + aoff, 16);
            cp_async16(st + TSZ + swz,     Alo + aoff, 16);
            int n = bn + r;
            uint32_t ok = (n < N) ? 16u : 0u;
            size_t boff = (size_t)(ok ? n : 0) * K + k0 + j * 8;
            cp_async16(st + 2 * TSZ + swz, Bhi + boff, ok);
            cp_async16(st + 3 * TSZ + swz, Blo + boff, ok);
        }
    };

    load_stage(0, 0);  cp_commit();
    load_stage(1, 64); cp_commit();

    const int rA = wm + (lane & 15);
    const int jA = lane >> 4;
    const int qB = lane >> 3;
    const int rB = wn + ((qB >= 2) ? 8 : 0) + (lane & 7);
    const int jB = qB & 1;

    int buf = 0;
    for (int ch = 0; ch < NC; ch++) {
        if (ch + 2 < NC) load_stage((buf + 2 >= 3) ? buf - 1 : buf + 2, (ch + 2) << 6);
        cp_commit();
        cp_wait2();
        __syncthreads();

        uint32_t stA  = sbase + buf * 4 * TSZ;
        uint32_t stAl = stA + TSZ;
        uint32_t stB  = stA + 2 * TSZ;
        uint32_t stBl = stA + 3 * TSZ;

#pragma unroll
        for (int ks = 0; ks < 4; ks++) {
            // B fragments: one x4 ldsm covers 16 n-rows x 16 k
            uint32_t bh[4], bl[4];
            {
                int r = rB;
                int jj = 2 * ks + jB;
                uint32_t off = (uint32_t)((r * 8 + (jj ^ (r & 7))) * 16);
                ldsm_x4(bh, stB  + off);
                ldsm_x4(bl, stBl + off);
            }
#pragma unroll
            for (int mi = 0; mi < 4; mi++) {
                uint32_t ah[4], al[4];
                int r = rA + mi * 16;
                int jj = 2 * ks + jA;
                uint32_t off = (uint32_t)((r * 8 + (jj ^ (r & 7))) * 16);
                ldsm_x4(ah, stA  + off);
                ldsm_x4(al, stAl + off);
#pragma unroll
                for (int ni = 0; ni < 2; ni++)
                    mma16816(acc[mi][ni], ah, &bh[ni * 2]);
#pragma unroll
                for (int ni = 0; ni < 2; ni++)
                    mma16816(acc[mi][ni], ah, &bl[ni * 2]);
#pragma unroll
                for (int ni = 0; ni < 2; ni++)
                    mma16816(acc[mi][ni], al, &bh[ni * 2]);
            }
        }
        __syncthreads();
        buf = (buf + 1 >= 3) ? 0 : buf + 1;
    }

    const int gid = lane >> 2, tig = lane & 3;
#pragma unroll
    for (int mi = 0; mi < 4; mi++) {
        int row = bm + wm + mi * 16 + gid;
        float s0 = 1.f, s1 = 1.f;
        if (row_sumsq) {
            s0 = rsqrtf(row_sumsq[row]     * (1.f / D_INNER) + 1e-6f);
            s1 = rsqrtf(row_sumsq[row + 8] * (1.f / D_INNER) + 1e-6f);
        }
#pragma unroll
        for (int ni = 0; ni < 2; ni++) {
            int col = bn + wn + ni * 8 + tig * 2;
            if (col < N) {
                float2 lo2 = make_float2(acc[mi][ni][0] * s0, acc[mi][ni][1] * s0);
                float2 hi2 = make_float2(acc[mi][ni][2] * s1, acc[mi][ni][3] * s1);
                *reinterpret_cast<float2*>(C + (size_t)row * N + col) = lo2;
                *reinterpret_cast<float2*>(C + (size_t)(row + 8) * N + col) = hi2;
            }
        }
    }
}

// ---------------- depthwise causal conv(4) + silu, with abar fused ----------
__global__ __launch_bounds__(256) void conv_silu_abar_kernel(
    const float* __restrict__ conv_w, const float* __restrict__ conv_b,
    const float* __restrict__ A_log, const float* __restrict__ dt_bias)
{
    int idx = blockIdx.x * 256 + threadIdx.x;
    {
        int c  = idx & (D_INNER - 1);
        int ml = idx >> 11;
        int l  = ml & (SEQ - 1);
        int b  = ml >> 10;

        float acc = conv_b[c];
#pragma unroll
        for (int k = 0; k < D_CONV; k++) {
            int ls = l + k - (D_CONV - 1);
            if (ls >= 0)
                acc = fmaf(g_zx[(size_t)(b * SEQ + ls) * D_IN_PROJ + D_INNER + c],
                           conv_w[c * D_CONV + k], acc);
        }
        acc = acc / (1.f + expf(-acc));
        g_xconv[idx] = acc;
    }
    if (blockIdx.x < (ML * N_HEADS) / 256) {
        int i2 = blockIdx.x * 256 + threadIdx.x;   // over ML*N_HEADS
        int h  = i2 & (N_HEADS - 1);
        int ml = i2 >> 3;
        float raw = g_zx[(size_t)ml * D_IN_PROJ + 2 * D_INNER + h] + dt_bias[h];
        float sp  = (raw > 20.f) ? raw : log1pf(expf(raw));
        g_abar[i2] = expf(-expf(A_log[h]) * sp);
    }
}

// ---------------- per-segment decay products + zero sumsq -------------------
__global__ __launch_bounds__(256) void aseg_kernel()
{
    int gidx = blockIdx.x * 256 + threadIdx.x;
    if (gidx < ML) g_sumsq[gidx] = 0.f;

    int w = blockIdx.x * 8 + (threadIdx.x >> 5);    // 0..127
    int lane = threadIdx.x & 31;
    int seg = w & 7;
    int h   = (w >> 3) & 7;
    int b   = w >> 6;
    int t0  = seg * SEG_LEN;
    float p = 1.f;
#pragma unroll
    for (int k = 0; k < 4; k++)
        p *= g_abar[(b * SEQ + t0 + lane * 4 + k) * N_HEADS + h];
#pragma unroll
    for (int o = 16; o; o >>= 1)
        p *= __shfl_xor_sync(0xFFFFFFFFu, p, o);
    if (lane == 0) g_aseg[w] = p;
}

// ---------------- scan pass A: per-segment local state (zero init) ----------
__global__ __launch_bounds__(128) void scan_partA()
{
    const int bx = blockIdx.x;
    const int dq = bx & 7, seg = (bx >> 3) & 7, h = (bx >> 6) & 7, b = bx >> 9;
    const int tid = threadIdx.x;
    const int q  = tid & 3;
    const int dl = tid >> 2;
    const int c0 = h * HEAD_DIM + dq * 32;

    float hs[16];
#pragma unroll
    for (int n = 0; n < 16; n++) hs[n] = 0.f;

    __shared__ float sB[2][4][64];
    __shared__ float sx[2][4][32];
    __shared__ float sa[2][4];

    const size_t rb = (size_t)b * SEQ + seg * SEG_LEN;

    auto load_group = [&](int g, int bb) {
        const int t0 = g * 4;
        if (tid < 64) {
            int st = tid >> 4, f = tid & 15;
            const float* p = g_zx + (rb + t0 + st) * D_IN_PROJ + 2 * D_INNER + N_HEADS + f * 4;
            *reinterpret_cast<float4*>(&sB[bb][st][f * 4]) = *reinterpret_cast<const float4*>(p);
        }
        { int st = tid >> 5, ii = tid & 31;
          sx[bb][st][ii] = g_xconv[(rb + t0 + st) * D_INNER + c0 + ii]; }
        if (tid < 4) sa[bb][tid] = g_abar[(rb + t0 + tid) * N_HEADS + h];
    };

    load_group(0, 0);
    __syncthreads();

    for (int g = 0; g < SEG_LEN / 4; g++) {
        const int bb = g & 1;
        if (g + 1 < SEG_LEN / 4) load_group(g + 1, bb ^ 1);
#pragma unroll
        for (int st = 0; st < 4; st++) {
            float a = sa[bb][st];
            float x = sx[bb][st][dl];
            const float4* Bv = reinterpret_cast<const float4*>(&sB[bb][st][q * 16]);
#pragma unroll
            for (int i = 0; i < 4; i++) {
                float4 bq = Bv[i];
                hs[i*4+0] = fmaf(a, hs[i*4+0], bq.x * x);
                hs[i*4+1] = fmaf(a, hs[i*4+1], bq.y * x);
                hs[i*4+2] = fmaf(a, hs[i*4+2], bq.z * x);
                hs[i*4+3] = fmaf(a, hs[i*4+3], bq.w * x);
            }
        }
        __syncthreads();
    }

    size_t base = (((size_t)(b * 8 + h) * 8 + seg) * (HEAD_DIM * D_STATE))
                + (size_t)(dq * 32 + dl) * 64 + q * 16;
#pragma unroll
    for (int i = 0; i < 4; i++)
        *reinterpret_cast<float4*>(&g_state[base + i * 4]) =
            make_float4(hs[i*4+0], hs[i*4+1], hs[i*4+2], hs[i*4+3]);
}

// ---------------- scan pass C: combine + scan + gate + bf16 split + sumsq ---
__global__ __launch_bounds__(128) void scan_partC(
    const float* __restrict__ D_param, const float* __restrict__ norm_w)
{
    const int bx = blockIdx.x;
    const int dq = bx & 7, seg = (bx >> 3) & 7, h = (bx >> 6) & 7, b = bx >> 9;
    const int tid = threadIdx.x;
    const int warp = tid >> 5;
    const int lane = tid & 31;
    const int q  = tid & 3;
    const int dl = tid >> 2;
    const int c0 = h * HEAD_DIM + dq * 32;
    const int c  = c0 + dl;
    const int bh = b * 8 + h;

    float hs[16];
#pragma unroll
    for (int n = 0; n < 16; n++) hs[n] = 0.f;
    if (seg > 0) {
        float f = 1.f;
        const size_t slice = (size_t)(dq * 32 + dl) * 64 + q * 16;
        for (int s = seg - 1; s >= 0; s--) {
            size_t base = ((size_t)bh * 8 + s) * (HEAD_DIM * D_STATE) + slice;
#pragma unroll
            for (int i = 0; i < 4; i++) {
                float4 v = *reinterpret_cast<const float4*>(&g_state[base + i * 4]);
                hs[i*4+0] = fmaf(f, v.x, hs[i*4+0]);
                hs[i*4+1] = fmaf(f, v.y, hs[i*4+1]);
                hs[i*4+2] = fmaf(f, v.z, hs[i*4+2]);
                hs[i*4+3] = fmaf(f, v.w, hs[i*4+3]);
            }
            f *= g_aseg[bh * 8 + s];
        }
    }

    __shared__ float sBC[2][4][128];
    __shared__ float sx[2][4][32];
    __shared__ float sz[2][4][32];
    __shared__ float sa[2][4];
    __shared__ float s_part[2][4][4];   // [bb][warp][st]

    const float Dp = D_param[h];
    const float wv = norm_w[c];
    const size_t rb = (size_t)b * SEQ + seg * SEG_LEN;

    auto load_group = [&](int g, int bb) {
        const int t0 = g * 4;
        {   int st = tid >> 5, f4 = tid & 31;
            const float* p = g_zx + (rb + t0 + st) * D_IN_PROJ + 2 * D_INNER + N_HEADS + f4 * 4;
            *reinterpret_cast<float4*>(&sBC[bb][st][f4 * 4]) = *reinterpret_cast<const float4*>(p); }
        {   int st = tid >> 5, ii = tid & 31;
            sx[bb][st][ii] = g_xconv[(rb + t0 + st) * D_INNER + c0 + ii];
            sz[bb][st][ii] = g_zx[(rb + t0 + st) * D_IN_PROJ + c0 + ii]; }
        if (tid < 4) sa[bb][tid] = g_abar[(rb + t0 + tid) * N_HEADS + h];
    };

    load_group(0, 0);
    __syncthreads();

    for (int g = 0; g < SEG_LEN / 4; g++) {
        const int bb = g & 1;
        if (g + 1 < SEG_LEN / 4) load_group(g + 1, bb ^ 1);
#pragma unroll
        for (int st = 0; st < 4; st++) {
            float a = sa[bb][st];
            float x = sx[bb][st][dl];
            const float4* Bv = reinterpret_cast<const float4*>(&sBC[bb][st][q * 16]);
            const float4* Cv = reinterpret_cast<const float4*>(&sBC[bb][st][64 + q * 16]);
            float y = 0.f;
#pragma unroll
            for (int i = 0; i < 4; i++) {
                float4 bq = Bv[i], cq = Cv[i];
                hs[i*4+0] = fmaf(a, hs[i*4+0], bq.x * x); y = fmaf(hs[i*4+0], cq.x, y);
                hs[i*4+1] = fmaf(a, hs[i*4+1], bq.y * x); y = fmaf(hs[i*4+1], cq.y, y);
                hs[i*4+2] = fmaf(a, hs[i*4+2], bq.z * x); y = fmaf(hs[i*4+2], cq.z, y);
                hs[i*4+3] = fmaf(a, hs[i*4+3], bq.w * x); y = fmaf(hs[i*4+3], cq.w, y);
            }
            y += __shfl_xor_sync(0xFFFFFFFFu, y, 1);
            y += __shfl_xor_sync(0xFFFFFFFFu, y, 2);
            float zv = sz[bb][st][dl];
            float gate = zv / (1.f + expf(-zv));
            float f = (y + Dp * x) * gate;
            float yy = f * f;
            yy += __shfl_xor_sync(0xFFFFFFFFu, yy, 4);
            yy += __shfl_xor_sync(0xFFFFFFFFu, yy, 8);
            yy += __shfl_xor_sync(0xFFFFFFFFu, yy, 16);
            if (lane == 0) s_part[bb][warp][st] = yy;
            if (q == 0) {
                float fw = f * wv;
                __nv_bfloat16 hbf = __float2bfloat16(fw);
                __nv_bfloat16 lbf = __float2bfloat16(fw - __bfloat162float(hbf));
                size_t off = (rb + g * 4 + st) * D_INNER + c;
                g_yhi[off] = hbf;
                g_ylo[off] = lbf;
            }
        }
        __syncthreads();
        if (tid < 4) {
            float tot = s_part[bb][0][tid] + s_part[bb][1][tid]
                      + s_part[bb][2][tid] + s_part[bb][3][tid];
            atomicAdd(&g_sumsq[rb + g * 4 + tid], tot);
        }
    }
}

// ---------------- launch ----------------------------------------------------
extern "C" void kernel_launch(void* const* d_in, const int* in_sizes, int n_in,
                              void* d_out, int out_size)
{
    const float* x          = (const float*)d_in[0];
    const float* in_proj_w  = (const float*)d_in[1];
    const float* conv_w     = (const float*)d_in[2];
    const float* conv_b     = (const float*)d_in[3];
    const float* A_log      = (const float*)d_in[4];
    const float* D_param    = (const float*)d_in[5];
    const float* dt_bias    = (const float*)d_in[6];
    const float* norm_w     = (const float*)d_in[7];
    const float* out_proj_w = (const float*)d_in[8];
    float* out = (float*)d_out;

    float *p_zx, *p_sumsq;
    __nv_bfloat16 *p_xhi, *p_xlo, *p_w1hi, *p_w1lo, *p_yhi, *p_ylo, *p_w2hi, *p_w2lo;
    cudaGetSymbolAddress((void**)&p_zx,    g_zx);
    cudaGetSymbolAddress((void**)&p_sumsq, g_sumsq);
    cudaGetSymbolAddress((void**)&p_xhi,   g_xhi);
    cudaGetSymbolAddress((void**)&p_xlo,   g_xlo);
    cudaGetSymbolAddress((void**)&p_w1hi,  g_w1hi);
    cudaGetSymbolAddress((void**)&p_w1lo,  g_w1lo);
    cudaGetSymbolAddress((void**)&p_yhi,   g_yhi);
    cudaGetSymbolAddress((void**)&p_ylo,   g_ylo);
    cudaGetSymbolAddress((void**)&p_w2hi,  g_w2hi);
    cudaGetSymbolAddress((void**)&p_w2lo,  g_w2lo);

    const int dyn_smem = 12 * TSZ;   // 192KB (3 stages)
    cudaFuncSetAttribute(gemm_mma, cudaFuncAttributeMaxDynamicSharedMemorySize, dyn_smem);

    // 0. split all fp32 inputs to bf16 hi/lo (one launch)
    {
        int total = N4X + N4W1 + N4W2;
        split_all<<<(total + 255) / 256, 256>>>(x, in_proj_w, out_proj_w);
    }
    // 1. in_proj (no row scale)
    {
        dim3 grid((D_IN_PROJ + 127) / 128, ML / 128);
        gemm_mma<<<grid, 512, dyn_smem>>>(p_xhi, p_xlo, p_w1hi, p_w1lo,
                                          p_zx, ML, D_IN_PROJ, DIMM, nullptr);
    }
    // 2. conv + silu (+ a_bar fused)
    conv_silu_abar_kernel<<<(ML * D_INNER) / 256, 256>>>(conv_w, conv_b, A_log, dt_bias);
    // 3. segment decay products + zero sumsq
    aseg_kernel<<<16, 256>>>();
    // 4. two-level scan; pass C emits bf16 (y*w) hi/lo + row sumsq
    scan_partA<<<1024, 128>>>();
    scan_partC<<<1024, 128>>>(D_param, norm_w);
    // 5. out_proj with fused rmsnorm row scale
    {
        dim3 grid(DIMM / 128, ML / 128);
        gemm_mma<<<grid, 512, dyn_smem>>>(p_yhi, p_ylo, p_w2hi, p_w2lo,
                                          out, ML, DIMM, D_INNER, p_sumsq);
    }
}

// round 12
// speedup vs baseline: 1.0514x; 1.0514x over previous
#include <cuda_runtime.h>
#include <cuda_bf16.h>
#include <math.h>
#include <stdint.h>

#define BATCH    2
#define SEQ      1024
#define DIMM     1024
#define D_STATE  64
#define D_CONV   4
#define N_HEADS  8
#define D_INNER  2048
#define HEAD_DIM 256
#define D_IN_PROJ 4232          // 2048 + 2048 + 8 + 64 + 64
#define ML       (BATCH*SEQ)    // 2048
#define NSEG     8
#define SEG_LEN  128            // SEQ / NSEG

// ---------------- scratch (device globals: allocation-free) ----------------
__device__ float g_zx[(size_t)ML * D_IN_PROJ];      // in_proj output
__device__ float g_xconv[(size_t)ML * D_INNER];     // silu(conv(xc)) == xh
__device__ float g_y[(size_t)ML * D_INNER];         // (y+Dx)*silu(z)
__device__ float g_abar[ML * N_HEADS];
__device__ float g_aseg[BATCH * N_HEADS * NSEG];    // per-segment decay product
__device__ float g_state[(size_t)BATCH * N_HEADS * NSEG * HEAD_DIM * D_STATE]; // 8MB

// bf16 hi/lo split buffers
__device__ __nv_bfloat16 g_xhi[(size_t)ML * DIMM];
__device__ __nv_bfloat16 g_xlo[(size_t)ML * DIMM];
__device__ __nv_bfloat16 g_w1hi[(size_t)D_IN_PROJ * DIMM];
__device__ __nv_bfloat16 g_w1lo[(size_t)D_IN_PROJ * DIMM];
__device__ __nv_bfloat16 g_yhi[(size_t)ML * D_INNER];
__device__ __nv_bfloat16 g_ylo[(size_t)ML * D_INNER];
__device__ __nv_bfloat16 g_w2hi[(size_t)DIMM * D_INNER];
__device__ __nv_bfloat16 g_w2lo[(size_t)DIMM * D_INNER];

// ---------------- PTX helpers (sm_80-era, compute_103-safe) ----------------
__device__ __forceinline__ uint32_t smem_u32(const void* p) {
    uint32_t a;
    asm("{ .reg .u64 t; cvta.to.shared.u64 t, %1; cvt.u32.u64 %0, t; }"
        : "=r"(a) : "l"(p));
    return a;
}
__device__ __forceinline__ void cp_async16(uint32_t saddr, const void* gaddr, uint32_t srcsz) {
    asm volatile("cp.async.cg.shared.global [%0], [%1], 16, %2;"
                 :: "r"(saddr), "l"(gaddr), "r"(srcsz) : "memory");
}
__device__ __forceinline__ void cp_commit() {
    asm volatile("cp.async.commit_group;" ::: "memory");
}
__device__ __forceinline__ void cp_wait1() {
    asm volatile("cp.async.wait_group 1;" ::: "memory");
}
__device__ __forceinline__ void ldsm_x4(uint32_t* r, uint32_t addr) {
    asm volatile("ldmatrix.sync.aligned.m8n8.x4.shared.b16 {%0,%1,%2,%3}, [%4];"
                 : "=r"(r[0]), "=r"(r[1]), "=r"(r[2]), "=r"(r[3]) : "r"(addr));
}
__device__ __forceinline__ void mma16816(float* c, const uint32_t* a, const uint32_t* b) {
    asm volatile(
        "mma.sync.aligned.m16n8k16.row.col.f32.bf16.bf16.f32 "
        "{%0,%1,%2,%3}, {%4,%5,%6,%7}, {%8,%9}, {%0,%1,%2,%3};"
        : "+f"(c[0]), "+f"(c[1]), "+f"(c[2]), "+f"(c[3])
        : "r"(a[0]), "r"(a[1]), "r"(a[2]), "r"(a[3]), "r"(b[0]), "r"(b[1]));
}

// ---------------- fused fp32 -> bf16 hi/lo split for x, w1, w2 --------------
#define N4X  (ML * DIMM / 4)            // 524288
#define N4W1 (D_IN_PROJ * DIMM / 4)     // 1083392
#define N4W2 (DIMM * D_INNER / 4)       // 524288
__global__ __launch_bounds__(256) void split_all(
    const float* __restrict__ x, const float* __restrict__ w1,
    const float* __restrict__ w2)
{
    int i = blockIdx.x * 256 + threadIdx.x;
    const float* s;
    __nv_bfloat16 *hi, *lo;
    int j;
    if (i < N4X) { s = x; hi = g_xhi; lo = g_xlo; j = i; }
    else if (i < N4X + N4W1) { s = w1; hi = g_w1hi; lo = g_w1lo; j = i - N4X; }
    else if (i < N4X + N4W1 + N4W2) { s = w2; hi = g_w2hi; lo = g_w2lo; j = i - N4X - N4W1; }
    else return;

    float4 v = reinterpret_cast<const float4*>(s)[j];
    __nv_bfloat16 h0 = __float2bfloat16(v.x);
    __nv_bfloat16 h1 = __float2bfloat16(v.y);
    __nv_bfloat16 h2 = __float2bfloat16(v.z);
    __nv_bfloat16 h3 = __float2bfloat16(v.w);
    __nv_bfloat16 l0 = __float2bfloat16(v.x - __bfloat162float(h0));
    __nv_bfloat16 l1 = __float2bfloat16(v.y - __bfloat162float(h1));
    __nv_bfloat16 l2 = __float2bfloat16(v.z - __bfloat162float(h2));
    __nv_bfloat16 l3 = __float2bfloat16(v.w - __bfloat162float(h3));
    __nv_bfloat162 hh0{h0, h1}, hh1{h2, h3}, ll0{l0, l1}, ll1{l2, l3};
    reinterpret_cast<__nv_bfloat162*>(hi)[j * 2 + 0] = hh0;
    reinterpret_cast<__nv_bfloat162*>(hi)[j * 2 + 1] = hh1;
    reinterpret_cast<__nv_bfloat162*>(lo)[j * 2 + 0] = ll0;
    reinterpret_cast<__nv_bfloat162*>(lo)[j * 2 + 1] = ll1;
}

// ---------------- mma.sync GEMM (bf16x3, 3-stage, 1 barrier/chunk) ----------
// CTA: 128x128 tile, BK=64, 256 threads = 8 warps (2M x 4N), warp tile 64x32.
// Iter ch: wait1 (groups 0..ch done; committed so far = 0..ch+1) -> sync
// (all warps done computing ch-1, whose ring slot is being refilled) ->
// prefetch ch+2 -> ALWAYS commit -> compute ch. No final-chunk race.
#define TSZ 16384
__global__ __launch_bounds__(256, 1) void gemm_mma(
    const __nv_bfloat16* __restrict__ Ahi, const __nv_bfloat16* __restrict__ Alo,
    const __nv_bfloat16* __restrict__ Bhi, const __nv_bfloat16* __restrict__ Blo,
    float* __restrict__ C, int M, int N, int K)
{
    extern __shared__ char smem[];
    const int tid  = threadIdx.x;
    const int wid  = tid >> 5;
    const int lane = tid & 31;
    const int bm = blockIdx.y * 128, bn = blockIdx.x * 128;
    const int wm = (wid >> 2) * 64;
    const int wn = (wid & 3) * 32;

    const uint32_t sbase = smem_u32(smem);

    float acc[4][4][4];
#pragma unroll
    for (int mi = 0; mi < 4; mi++)
#pragma unroll
        for (int ni = 0; ni < 4; ni++)
#pragma unroll
            for (int v = 0; v < 4; v++) acc[mi][ni][v] = 0.f;

    const int NC = K >> 6;

    auto load_stage = [&](int buf, int k0) {
        uint32_t st = sbase + buf * 4 * TSZ;
#pragma unroll
        for (int it = 0; it < 4; it++) {
            int cid = it * 256 + tid;
            int r = cid >> 3, j = cid & 7;
            uint32_t swz = (uint32_t)((r * 8 + (j ^ (r & 7))) * 16);
            size_t aoff = (size_t)(bm + r) * K + k0 + j * 8;
            cp_async16(st + swz,           Ahi + aoff, 16);
            cp_async16(st + TSZ + swz,     Alo + aoff, 16);
            int n = bn + r;
            uint32_t ok = (n < N) ? 16u : 0u;
            size_t boff = (size_t)(ok ? n : 0) * K + k0 + j * 8;
            cp_async16(st + 2 * TSZ + swz, Bhi + boff, ok);
            cp_async16(st + 3 * TSZ + swz, Blo + boff, ok);
        }
    };

    load_stage(0, 0);  cp_commit();
    load_stage(1, 64); cp_commit();

    const int rA = wm + (lane & 15);
    const int jA = lane >> 4;
    const int qB = lane >> 3;
    const int rB = wn + ((qB >= 2) ? 8 : 0) + (lane & 7);
    const int jB = qB & 1;

    int buf = 0;
    for (int ch = 0; ch < NC; ch++) {
        cp_wait1();          // committed 0..ch+1 -> groups 0..ch complete
        __syncthreads();     // all warps finished stage ch-1 (slot being refilled)
        if (ch + 2 < NC) load_stage((buf + 2 >= 3) ? buf - 1 : buf + 2, (ch + 2) << 6);
        cp_commit();         // always commit (possibly empty group)

        uint32_t stA  = sbase + buf * 4 * TSZ;
        uint32_t stAl = stA + TSZ;
        uint32_t stB  = stA + 2 * TSZ;
        uint32_t stBl = stA + 3 * TSZ;

#pragma unroll
        for (int ks = 0; ks < 4; ks++) {
            uint32_t bh[2][4], bl[2][4];
#pragma unroll
            for (int np = 0; np < 2; np++) {
                int r = rB + np * 16;
                int jj = 2 * ks + jB;
                uint32_t off = (uint32_t)((r * 8 + (jj ^ (r & 7))) * 16);
                ldsm_x4(bh[np], stB  + off);
                ldsm_x4(bl[np], stBl + off);
            }
#pragma unroll
            for (int mi = 0; mi < 4; mi++) {
                uint32_t ah[4], al[4];
                int r = rA + mi * 16;
                int jj = 2 * ks + jA;
                uint32_t off = (uint32_t)((r * 8 + (jj ^ (r & 7))) * 16);
                ldsm_x4(ah, stA  + off);
                ldsm_x4(al, stAl + off);
#pragma unroll
                for (int ni = 0; ni < 4; ni++)
                    mma16816(acc[mi][ni], ah, &bh[ni >> 1][(ni & 1) * 2]);
#pragma unroll
                for (int ni = 0; ni < 4; ni++)
                    mma16816(acc[mi][ni], ah, &bl[ni >> 1][(ni & 1) * 2]);
#pragma unroll
                for (int ni = 0; ni < 4; ni++)
                    mma16816(acc[mi][ni], al, &bh[ni >> 1][(ni & 1) * 2]);
            }
        }
        buf = (buf + 1 >= 3) ? 0 : buf + 1;
    }

    const int gid = lane >> 2, tig = lane & 3;
#pragma unroll
    for (int mi = 0; mi < 4; mi++) {
        int row = bm + wm + mi * 16 + gid;
#pragma unroll
        for (int ni = 0; ni < 4; ni++) {
            int col = bn + wn + ni * 8 + tig * 2;
            if (col < N) {
                float2 lo2 = make_float2(acc[mi][ni][0], acc[mi][ni][1]);
                float2 hi2 = make_float2(acc[mi][ni][2], acc[mi][ni][3]);
                *reinterpret_cast<float2*>(C + (size_t)row * N + col) = lo2;
                *reinterpret_cast<float2*>(C + (size_t)(row + 8) * N + col) = hi2;
            }
        }
    }
}

// ---------------- depthwise causal conv(4) + silu, with abar fused ----------
__global__ __launch_bounds__(256) void conv_silu_abar_kernel(
    const float* __restrict__ conv_w, const float* __restrict__ conv_b,
    const float* __restrict__ A_log, const float* __restrict__ dt_bias)
{
    int idx = blockIdx.x * 256 + threadIdx.x;
    {
        int c  = idx & (D_INNER - 1);
        int ml = idx >> 11;
        int l  = ml & (SEQ - 1);
        int b  = ml >> 10;

        float acc = conv_b[c];
#pragma unroll
        for (int k = 0; k < D_CONV; k++) {
            int ls = l + k - (D_CONV - 1);
            if (ls >= 0)
                acc = fmaf(g_zx[(size_t)(b * SEQ + ls) * D_IN_PROJ + D_INNER + c],
                           conv_w[c * D_CONV + k], acc);
        }
        acc = acc / (1.f + expf(-acc));
        g_xconv[idx] = acc;
    }
    if (blockIdx.x < (ML * N_HEADS) / 256) {
        int i2 = blockIdx.x * 256 + threadIdx.x;   // over ML*N_HEADS
        int h  = i2 & (N_HEADS - 1);
        int ml = i2 >> 3;
        float raw = g_zx[(size_t)ml * D_IN_PROJ + 2 * D_INNER + h] + dt_bias[h];
        float sp  = (raw > 20.f) ? raw : log1pf(expf(raw));
        g_abar[i2] = expf(-expf(A_log[h]) * sp);
    }
}

// ---------------- per-segment decay products (1 warp per (b,h,seg)) ---------
__global__ __launch_bounds__(256) void aseg_kernel()
{
    int w = blockIdx.x * 8 + (threadIdx.x >> 5);    // 0..127
    int lane = threadIdx.x & 31;
    int seg = w & 7;
    int h   = (w >> 3) & 7;
    int b   = w >> 6;
    int t0  = seg * SEG_LEN;
    float p = 1.f;
#pragma unroll
    for (int k = 0; k < 4; k++)
        p *= g_abar[(b * SEQ + t0 + lane * 4 + k) * N_HEADS + h];
#pragma unroll
    for (int o = 16; o; o >>= 1)
        p *= __shfl_xor_sync(0xFFFFFFFFu, p, o);
    if (lane == 0) g_aseg[w] = p;
}

// ---------------- scan pass A: per-segment local state (zero init) ----------
__global__ __launch_bounds__(128) void scan_partA()
{
    const int bx = blockIdx.x;
    const int dq = bx & 7, seg = (bx >> 3) & 7, h = (bx >> 6) & 7, b = bx >> 9;
    const int tid = threadIdx.x;
    const int q  = tid & 3;
    const int dl = tid >> 2;
    const int c0 = h * HEAD_DIM + dq * 32;

    float hs[16];
#pragma unroll
    for (int n = 0; n < 16; n++) hs[n] = 0.f;

    __shared__ float sB[2][4][64];
    __shared__ float sx[2][4][32];
    __shared__ float sa[2][4];

    const size_t rb = (size_t)b * SEQ + seg * SEG_LEN;

    auto load_group = [&](int g, int bb) {
        const int t0 = g * 4;
        if (tid < 64) {
            int st = tid >> 4, f = tid & 15;
            const float* p = g_zx + (rb + t0 + st) * D_IN_PROJ + 2 * D_INNER + N_HEADS + f * 4;
            *reinterpret_cast<float4*>(&sB[bb][st][f * 4]) = *reinterpret_cast<const float4*>(p);
        }
        { int st = tid >> 5, ii = tid & 31;
          sx[bb][st][ii] = g_xconv[(rb + t0 + st) * D_INNER + c0 + ii]; }
        if (tid < 4) sa[bb][tid] = g_abar[(rb + t0 + tid) * N_HEADS + h];
    };

    load_group(0, 0);
    __syncthreads();

    for (int g = 0; g < SEG_LEN / 4; g++) {
        const int bb = g & 1;
        if (g + 1 < SEG_LEN / 4) load_group(g + 1, bb ^ 1);
#pragma unroll
        for (int st = 0; st < 4; st++) {
            float a = sa[bb][st];
            float x = sx[bb][st][dl];
            const float4* Bv = reinterpret_cast<const float4*>(&sB[bb][st][q * 16]);
#pragma unroll
            for (int i = 0; i < 4; i++) {
                float4 bq = Bv[i];
                hs[i*4+0] = fmaf(a, hs[i*4+0], bq.x * x);
                hs[i*4+1] = fmaf(a, hs[i*4+1], bq.y * x);
                hs[i*4+2] = fmaf(a, hs[i*4+2], bq.z * x);
                hs[i*4+3] = fmaf(a, hs[i*4+3], bq.w * x);
            }
        }
        __syncthreads();
    }

    size_t base = (((size_t)(b * 8 + h) * 8 + seg) * (HEAD_DIM * D_STATE))
                + (size_t)(dq * 32 + dl) * 64 + q * 16;
#pragma unroll
    for (int i = 0; i < 4; i++)
        *reinterpret_cast<float4*>(&g_state[base + i * 4]) =
            make_float4(hs[i*4+0], hs[i*4+1], hs[i*4+2], hs[i*4+3]);
}

// ---------------- scan pass C: inline combine + local scan + y + gate -------
__global__ __launch_bounds__(128) void scan_partC(const float* __restrict__ D_param)
{
    const int bx = blockIdx.x;
    const int dq = bx & 7, seg = (bx >> 3) & 7, h = (bx >> 6) & 7, b = bx >> 9;
    const int tid = threadIdx.x;
    const int q  = tid & 3;
    const int dl = tid >> 2;
    const int c0 = h * HEAD_DIM + dq * 32;
    const int c  = c0 + dl;
    const int bh = b * 8 + h;

    float hs[16];
#pragma unroll
    for (int n = 0; n < 16; n++) hs[n] = 0.f;
    if (seg > 0) {
        float f = 1.f;
        const size_t slice = (size_t)(dq * 32 + dl) * 64 + q * 16;
        for (int s = seg - 1; s >= 0; s--) {
            size_t base = ((size_t)bh * 8 + s) * (HEAD_DIM * D_STATE) + slice;
#pragma unroll
            for (int i = 0; i < 4; i++) {
                float4 v = *reinterpret_cast<const float4*>(&g_state[base + i * 4]);
                hs[i*4+0] = fmaf(f, v.x, hs[i*4+0]);
                hs[i*4+1] = fmaf(f, v.y, hs[i*4+1]);
                hs[i*4+2] = fmaf(f, v.z, hs[i*4+2]);
                hs[i*4+3] = fmaf(f, v.w, hs[i*4+3]);
            }
            f *= g_aseg[bh * 8 + s];
        }
    }

    __shared__ float sBC[2][4][128];
    __shared__ float sx[2][4][32];
    __shared__ float sz[2][4][32];
    __shared__ float sa[2][4];

    const float Dp = D_param[h];
    const size_t rb = (size_t)b * SEQ + seg * SEG_LEN;

    auto load_group = [&](int g, int bb) {
        const int t0 = g * 4;
        {   int st = tid >> 5, f4 = tid & 31;
            const float* p = g_zx + (rb + t0 + st) * D_IN_PROJ + 2 * D_INNER + N_HEADS + f4 * 4;
            *reinterpret_cast<float4*>(&sBC[bb][st][f4 * 4]) = *reinterpret_cast<const float4*>(p); }
        {   int st = tid >> 5, ii = tid & 31;
            sx[bb][st][ii] = g_xconv[(rb + t0 + st) * D_INNER + c0 + ii];
            sz[bb][st][ii] = g_zx[(rb + t0 + st) * D_IN_PROJ + c0 + ii]; }
        if (tid < 4) sa[bb][tid] = g_abar[(rb + t0 + tid) * N_HEADS + h];
    };

    load_group(0, 0);
    __syncthreads();

    for (int g = 0; g < SEG_LEN / 4; g++) {
        const int bb = g & 1;
        if (g + 1 < SEG_LEN / 4) load_group(g + 1, bb ^ 1);
#pragma unroll
        for (int st = 0; st < 4; st++) {
            float a = sa[bb][st];
            float x = sx[bb][st][dl];
            const float4* Bv = reinterpret_cast<const float4*>(&sBC[bb][st][q * 16]);
            const float4* Cv = reinterpret_cast<const float4*>(&sBC[bb][st][64 + q * 16]);
            float y = 0.f;
#pragma unroll
            for (int i = 0; i < 4; i++) {
                float4 bq = Bv[i], cq = Cv[i];
                hs[i*4+0] = fmaf(a, hs[i*4+0], bq.x * x); y = fmaf(hs[i*4+0], cq.x, y);
                hs[i*4+1] = fmaf(a, hs[i*4+1], bq.y * x); y = fmaf(hs[i*4+1], cq.y, y);
                hs[i*4+2] = fmaf(a, hs[i*4+2], bq.z * x); y = fmaf(hs[i*4+2], cq.z, y);
                hs[i*4+3] = fmaf(a, hs[i*4+3], bq.w * x); y = fmaf(hs[i*4+3], cq.w, y);
            }
            y += __shfl_xor_sync(0xFFFFFFFFu, y, 1);
            y += __shfl_xor_sync(0xFFFFFFFFu, y, 2);
            if (q == 0) {
                float zv = sz[bb][st][dl];
                float gate = zv / (1.f + expf(-zv));
                g_y[(rb + g * 4 + st) * D_INNER + c] = (y + Dp * x) * gate;
            }
        }
        __syncthreads();
    }
}

// ---------------- rmsnorm + bf16 hi/lo split fused ---------------------------
__global__ __launch_bounds__(256) void rmsnorm_split_kernel(const float* __restrict__ norm_w)
{
    const int row = blockIdx.x;
    const float* y = g_y + (size_t)row * D_INNER;
    float4 v[2];
    float s = 0.f;
#pragma unroll
    for (int it = 0; it < 2; it++) {
        v[it] = reinterpret_cast<const float4*>(y)[threadIdx.x + it * 256];
        s = fmaf(v[it].x, v[it].x, s);
        s = fmaf(v[it].y, v[it].y, s);
        s = fmaf(v[it].z, v[it].z, s);
        s = fmaf(v[it].w, v[it].w, s);
    }
#pragma unroll
    for (int o = 16; o; o >>= 1) s += __shfl_xor_sync(0xFFFFFFFFu, s, o);
    __shared__ float red[8];
    if ((threadIdx.x & 31) == 0) red[threadIdx.x >> 5] = s;
    __syncthreads();
    if (threadIdx.x < 8) {
        s = red[threadIdx.x];
#pragma unroll
        for (int o = 4; o; o >>= 1) s += __shfl_xor_sync(0xFFu, s, o);
        if (threadIdx.x == 0) red[0] = s;
    }
    __syncthreads();
    const float scale = rsqrtf(red[0] * (1.f / D_INNER) + 1e-6f);

    __nv_bfloat16* hi = g_yhi + (size_t)row * D_INNER;
    __nv_bfloat16* lo = g_ylo + (size_t)row * D_INNER;
#pragma unroll
    for (int it = 0; it < 2; it++) {
        int i4 = threadIdx.x + it * 256;
        float4 w = reinterpret_cast<const float4*>(norm_w)[i4];
        float f0 = v[it].x * scale * w.x;
        float f1 = v[it].y * scale * w.y;
        float f2 = v[it].z * scale * w.z;
        float f3 = v[it].w * scale * w.w;
        __nv_bfloat16 h0 = __float2bfloat16(f0);
        __nv_bfloat16 h1 = __float2bfloat16(f1);
        __nv_bfloat16 h2 = __float2bfloat16(f2);
        __nv_bfloat16 h3 = __float2bfloat16(f3);
        __nv_bfloat16 l0 = __float2bfloat16(f0 - __bfloat162float(h0));
        __nv_bfloat16 l1 = __float2bfloat16(f1 - __bfloat162float(h1));
        __nv_bfloat16 l2 = __float2bfloat16(f2 - __bfloat162float(h2));
        __nv_bfloat16 l3 = __float2bfloat16(f3 - __bfloat162float(h3));
        __nv_bfloat162 hh0{h0, h1}, hh1{h2, h3}, ll0{l0, l1}, ll1{l2, l3};
        reinterpret_cast<__nv_bfloat162*>(hi)[i4 * 2 + 0] = hh0;
        reinterpret_cast<__nv_bfloat162*>(hi)[i4 * 2 + 1] = hh1;
        reinterpret_cast<__nv_bfloat162*>(lo)[i4 * 2 + 0] = ll0;
        reinterpret_cast<__nv_bfloat162*>(lo)[i4 * 2 + 1] = ll1;
    }
}

// ---------------- launch ----------------------------------------------------
extern "C" void kernel_launch(void* const* d_in, const int* in_sizes, int n_in,
                              void* d_out, int out_size)
{
    const float* x          = (const float*)d_in[0];
    const float* in_proj_w  = (const float*)d_in[1];
    const float* conv_w     = (const float*)d_in[2];
    const float* conv_b     = (const float*)d_in[3];
    const float* A_log      = (const float*)d_in[4];
    const float* D_param    = (const float*)d_in[5];
    const float* dt_bias    = (const float*)d_in[6];
    const float* norm_w     = (const float*)d_in[7];
    const float* out_proj_w = (const float*)d_in[8];
    float* out = (float*)d_out;

    float *p_zx;
    __nv_bfloat16 *p_xhi, *p_xlo, *p_w1hi, *p_w1lo, *p_yhi, *p_ylo, *p_w2hi, *p_w2lo;
    cudaGetSymbolAddress((void**)&p_zx,   g_zx);
    cudaGetSymbolAddress((void**)&p_xhi,  g_xhi);
    cudaGetSymbolAddress((void**)&p_xlo,  g_xlo);
    cudaGetSymbolAddress((void**)&p_w1hi, g_w1hi);
    cudaGetSymbolAddress((void**)&p_w1lo, g_w1lo);
    cudaGetSymbolAddress((void**)&p_yhi,  g_yhi);
    cudaGetSymbolAddress((void**)&p_ylo,  g_ylo);
    cudaGetSymbolAddress((void**)&p_w2hi, g_w2hi);
    cudaGetSymbolAddress((void**)&p_w2lo, g_w2lo);

    const int dyn_smem = 12 * TSZ;   // 192KB (3 stages)
    cudaFuncSetAttribute(gemm_mma, cudaFuncAttributeMaxDynamicSharedMemorySize, dyn_smem);

    // 0. split all fp32 inputs to bf16 hi/lo (one launch)
    {
        int total = N4X + N4W1 + N4W2;
        split_all<<<(total + 255) / 256, 256>>>(x, in_proj_w, out_proj_w);
    }
    // 1. in_proj
    {
        dim3 grid((D_IN_PROJ + 127) / 128, ML / 128);
        gemm_mma<<<grid, 256, dyn_smem>>>(p_xhi, p_xlo, p_w1hi, p_w1lo,
                                          p_zx, ML, D_IN_PROJ, DIMM);
    }
    // 2. conv + silu (+ a_bar fused)
    conv_silu_abar_kernel<<<(ML * D_INNER) / 256, 256>>>(conv_w, conv_b, A_log, dt_bias);
    // 3. segment decay products (parallel)
    aseg_kernel<<<16, 256>>>();
    // 4. two-level scan (combine inlined into pass C)
    scan_partA<<<1024, 128>>>();
    scan_partC<<<1024, 128>>>(D_param);
    // 5. rmsnorm + y split fused
    rmsnorm_split_kernel<<<ML, 256>>>(norm_w);
    // 6. out_proj
    {
        dim3 grid(DIMM / 128, ML / 128);
        gemm_mma<<<grid, 256, dyn_smem>>>(p_yhi, p_ylo, p_w2hi, p_w2lo,
                                          out, ML, DIMM, D_INNER);
    }
}

// round 13
// speedup vs baseline: 1.0582x; 1.0064x over previous
#include <cuda_runtime.h>
#include <cuda_bf16.h>
#include <math.h>
#include <stdint.h>

#define BATCH    2
#define SEQ      1024
#define DIMM     1024
#define D_STATE  64
#define D_CONV   4
#define N_HEADS  8
#define D_INNER  2048
#define HEAD_DIM 256
#define D_IN_PROJ 4232          // 2048 + 2048 + 8 + 64 + 64
#define ML       (BATCH*SEQ)    // 2048
#define NSEG     8
#define SEG_LEN  128            // SEQ / NSEG

// ---------------- scratch (device globals: allocation-free) ----------------
__device__ float g_zx[(size_t)ML * D_IN_PROJ];      // in_proj output
__device__ float g_xconv[(size_t)ML * D_INNER];     // silu(conv(xc)) == xh
__device__ float g_y[(size_t)ML * D_INNER];         // (y+Dx)*silu(z)
__device__ float g_abar[ML * N_HEADS];
__device__ float g_aseg[BATCH * N_HEADS * NSEG];    // per-segment decay product
__device__ float g_state[(size_t)BATCH * N_HEADS * NSEG * HEAD_DIM * D_STATE]; // 8MB

// bf16 hi/lo split buffers
__device__ __nv_bfloat16 g_xhi[(size_t)ML * DIMM];
__device__ __nv_bfloat16 g_xlo[(size_t)ML * DIMM];
__device__ __nv_bfloat16 g_w1hi[(size_t)D_IN_PROJ * DIMM];
__device__ __nv_bfloat16 g_w1lo[(size_t)D_IN_PROJ * DIMM];
__device__ __nv_bfloat16 g_yhi[(size_t)ML * D_INNER];
__device__ __nv_bfloat16 g_ylo[(size_t)ML * D_INNER];
__device__ __nv_bfloat16 g_w2hi[(size_t)DIMM * D_INNER];
__device__ __nv_bfloat16 g_w2lo[(size_t)DIMM * D_INNER];

// ---------------- PTX helpers (sm_80-era, compute_103-safe) ----------------
__device__ __forceinline__ uint32_t smem_u32(const void* p) {
    uint32_t a;
    asm("{ .reg .u64 t; cvta.to.shared.u64 t, %1; cvt.u32.u64 %0, t; }"
        : "=r"(a) : "l"(p));
    return a;
}
__device__ __forceinline__ void cp_async16(uint32_t saddr, const void* gaddr, uint32_t srcsz) {
    asm volatile("cp.async.cg.shared.global [%0], [%1], 16, %2;"
                 :: "r"(saddr), "l"(gaddr), "r"(srcsz) : "memory");
}
__device__ __forceinline__ void cp_commit() {
    asm volatile("cp.async.commit_group;" ::: "memory");
}
__device__ __forceinline__ void cp_wait1() {
    asm volatile("cp.async.wait_group 1;" ::: "memory");
}
__device__ __forceinline__ void ldsm_x4(uint32_t* r, uint32_t addr) {
    asm volatile("ldmatrix.sync.aligned.m8n8.x4.shared.b16 {%0,%1,%2,%3}, [%4];"
                 : "=r"(r[0]), "=r"(r[1]), "=r"(r[2]), "=r"(r[3]) : "r"(addr));
}
__device__ __forceinline__ void mma16816(float* c, const uint32_t* a, const uint32_t* b) {
    asm volatile(
        "mma.sync.aligned.m16n8k16.row.col.f32.bf16.bf16.f32 "
        "{%0,%1,%2,%3}, {%4,%5,%6,%7}, {%8,%9}, {%0,%1,%2,%3};"
        : "+f"(c[0]), "+f"(c[1]), "+f"(c[2]), "+f"(c[3])
        : "r"(a[0]), "r"(a[1]), "r"(a[2]), "r"(a[3]), "r"(b[0]), "r"(b[1]));
}

// ---------------- fused fp32 -> bf16 hi/lo split for x, w1, w2 --------------
#define N4X  (ML * DIMM / 4)            // 524288
#define N4W1 (D_IN_PROJ * DIMM / 4)     // 1083392
#define N4W2 (DIMM * D_INNER / 4)       // 524288
__global__ __launch_bounds__(256) void split_all(
    const float* __restrict__ x, const float* __restrict__ w1,
    const float* __restrict__ w2)
{
    int i = blockIdx.x * 256 + threadIdx.x;
    const float* s;
    __nv_bfloat16 *hi, *lo;
    int j;
    if (i < N4X) { s = x; hi = g_xhi; lo = g_xlo; j = i; }
    else if (i < N4X + N4W1) { s = w1; hi = g_w1hi; lo = g_w1lo; j = i - N4X; }
    else if (i < N4X + N4W1 + N4W2) { s = w2; hi = g_w2hi; lo = g_w2lo; j = i - N4X - N4W1; }
    else return;

    float4 v = reinterpret_cast<const float4*>(s)[j];
    __nv_bfloat16 h0 = __float2bfloat16(v.x);
    __nv_bfloat16 h1 = __float2bfloat16(v.y);
    __nv_bfloat16 h2 = __float2bfloat16(v.z);
    __nv_bfloat16 h3 = __float2bfloat16(v.w);
    __nv_bfloat16 l0 = __float2bfloat16(v.x - __bfloat162float(h0));
    __nv_bfloat16 l1 = __float2bfloat16(v.y - __bfloat162float(h1));
    __nv_bfloat16 l2 = __float2bfloat16(v.z - __bfloat162float(h2));
    __nv_bfloat16 l3 = __float2bfloat16(v.w - __bfloat162float(h3));
    __nv_bfloat162 hh0{h0, h1}, hh1{h2, h3}, ll0{l0, l1}, ll1{l2, l3};
    reinterpret_cast<__nv_bfloat162*>(hi)[j * 2 + 0] = hh0;
    reinterpret_cast<__nv_bfloat162*>(hi)[j * 2 + 1] = hh1;
    reinterpret_cast<__nv_bfloat162*>(lo)[j * 2 + 0] = ll0;
    reinterpret_cast<__nv_bfloat162*>(lo)[j * 2 + 1] = ll1;
}

// ---------------- mma.sync GEMM (bf16x3, 3-stage, 1 barrier/chunk) ----------
#define TSZ 16384
__global__ __launch_bounds__(256, 1) void gemm_mma(
    const __nv_bfloat16* __restrict__ Ahi, const __nv_bfloat16* __restrict__ Alo,
    const __nv_bfloat16* __restrict__ Bhi, const __nv_bfloat16* __restrict__ Blo,
    float* __restrict__ C, int M, int N, int K)
{
    extern __shared__ char smem[];
    const int tid  = threadIdx.x;
    const int wid  = tid >> 5;
    const int lane = tid & 31;
    const int bm = blockIdx.y * 128, bn = blockIdx.x * 128;
    const int wm = (wid >> 2) * 64;
    const int wn = (wid & 3) * 32;

    const uint32_t sbase = smem_u32(smem);

    float acc[4][4][4];
#pragma unroll
    for (int mi = 0; mi < 4; mi++)
#pragma unroll
        for (int ni = 0; ni < 4; ni++)
#pragma unroll
            for (int v = 0; v < 4; v++) acc[mi][ni][v] = 0.f;

    const int NC = K >> 6;

    auto load_stage = [&](int buf, int k0) {
        uint32_t st = sbase + buf * 4 * TSZ;
#pragma unroll
        for (int it = 0; it < 4; it++) {
            int cid = it * 256 + tid;
            int r = cid >> 3, j = cid & 7;
            uint32_t swz = (uint32_t)((r * 8 + (j ^ (r & 7))) * 16);
            size_t aoff = (size_t)(bm + r) * K + k0 + j * 8;
            cp_async16(st + swz,           Ahi + aoff, 16);
            cp_async16(st + TSZ + swz,     Alo + aoff, 16);
            int n = bn + r;
            uint32_t ok = (n < N) ? 16u : 0u;
            size_t boff = (size_t)(ok ? n : 0) * K + k0 + j * 8;
            cp_async16(st + 2 * TSZ + swz, Bhi + boff, ok);
            cp_async16(st + 3 * TSZ + swz, Blo + boff, ok);
        }
    };

    load_stage(0, 0);  cp_commit();
    load_stage(1, 64); cp_commit();

    const int rA = wm + (lane & 15);
    const int jA = lane >> 4;
    const int qB = lane >> 3;
    const int rB = wn + ((qB >= 2) ? 8 : 0) + (lane & 7);
    const int jB = qB & 1;

    int buf = 0;
    for (int ch = 0; ch < NC; ch++) {
        cp_wait1();
        __syncthreads();
        if (ch + 2 < NC) load_stage((buf + 2 >= 3) ? buf - 1 : buf + 2, (ch + 2) << 6);
        cp_commit();

        uint32_t stA  = sbase + buf * 4 * TSZ;
        uint32_t stAl = stA + TSZ;
        uint32_t stB  = stA + 2 * TSZ;
        uint32_t stBl = stA + 3 * TSZ;

#pragma unroll
        for (int ks = 0; ks < 4; ks++) {
            uint32_t bh[2][4], bl[2][4];
#pragma unroll
            for (int np = 0; np < 2; np++) {
                int r = rB + np * 16;
                int jj = 2 * ks + jB;
                uint32_t off = (uint32_t)((r * 8 + (jj ^ (r & 7))) * 16);
                ldsm_x4(bh[np], stB  + off);
                ldsm_x4(bl[np], stBl + off);
            }
#pragma unroll
            for (int mi = 0; mi < 4; mi++) {
                uint32_t ah[4], al[4];
                int r = rA + mi * 16;
                int jj = 2 * ks + jA;
                uint32_t off = (uint32_t)((r * 8 + (jj ^ (r & 7))) * 16);
                ldsm_x4(ah, stA  + off);
                ldsm_x4(al, stAl + off);
#pragma unroll
                for (int ni = 0; ni < 4; ni++)
                    mma16816(acc[mi][ni], ah, &bh[ni >> 1][(ni & 1) * 2]);
#pragma unroll
                for (int ni = 0; ni < 4; ni++)
                    mma16816(acc[mi][ni], ah, &bl[ni >> 1][(ni & 1) * 2]);
#pragma unroll
                for (int ni = 0; ni < 4; ni++)
                    mma16816(acc[mi][ni], al, &bh[ni >> 1][(ni & 1) * 2]);
            }
        }
        buf = (buf + 1 >= 3) ? 0 : buf + 1;
    }

    const int gid = lane >> 2, tig = lane & 3;
#pragma unroll
    for (int mi = 0; mi < 4; mi++) {
        int row = bm + wm + mi * 16 + gid;
#pragma unroll
        for (int ni = 0; ni < 4; ni++) {
            int col = bn + wn + ni * 8 + tig * 2;
            if (col < N) {
                float2 lo2 = make_float2(acc[mi][ni][0], acc[mi][ni][1]);
                float2 hi2 = make_float2(acc[mi][ni][2], acc[mi][ni][3]);
                *reinterpret_cast<float2*>(C + (size_t)row * N + col) = lo2;
                *reinterpret_cast<float2*>(C + (size_t)(row + 8) * N + col) = hi2;
            }
        }
    }
}

// ---------------- depthwise causal conv(4) + silu (pure) --------------------
__global__ __launch_bounds__(256) void conv_silu_kernel(
    const float* __restrict__ conv_w, const float* __restrict__ conv_b)
{
    int idx = blockIdx.x * 256 + threadIdx.x;
    int c  = idx & (D_INNER - 1);
    int ml = idx >> 11;
    int l  = ml & (SEQ - 1);
    int b  = ml >> 10;

    float acc = conv_b[c];
#pragma unroll
    for (int k = 0; k < D_CONV; k++) {
        int ls = l + k - (D_CONV - 1);
        if (ls >= 0)
            acc = fmaf(g_zx[(size_t)(b * SEQ + ls) * D_IN_PROJ + D_INNER + c],
                       conv_w[c * D_CONV + k], acc);
    }
    acc = acc / (1.f + expf(-acc));
    g_xconv[idx] = acc;
}

// ---------------- abar + per-segment decay product (1 warp per (b,h,seg)) ---
// 128 tuples; each warp computes its segment's 128 abar values and product.
__global__ __launch_bounds__(256) void abar_aseg_kernel(
    const float* __restrict__ A_log, const float* __restrict__ dt_bias)
{
    int w = blockIdx.x * 8 + (threadIdx.x >> 5);    // 0..127
    int lane = threadIdx.x & 31;
    int seg = w & 7;
    int h   = (w >> 3) & 7;
    int b   = w >> 6;
    int t0  = seg * SEG_LEN;
    const float negA = -expf(A_log[h]);
    const float db   = dt_bias[h];
    float p = 1.f;
#pragma unroll
    for (int k = 0; k < 4; k++) {
        int t = t0 + lane * 4 + k;
        float raw = g_zx[(size_t)(b * SEQ + t) * D_IN_PROJ + 2 * D_INNER + h] + db;
        float sp  = (raw > 20.f) ? raw : log1pf(expf(raw));
        float a   = expf(negA * sp);
        g_abar[(b * SEQ + t) * N_HEADS + h] = a;
        p *= a;
    }
#pragma unroll
    for (int o = 16; o; o >>= 1)
        p *= __shfl_xor_sync(0xFFFFFFFFu, p, o);
    if (lane == 0) g_aseg[w] = p;
}

// ---------------- scan pass A: per-segment local state (zero init) ----------
// grid 1024: (b,h,seg,dq). 128 threads: 4/d, 32 d per CTA. 8-step groups.
__global__ __launch_bounds__(128) void scan_partA()
{
    const int bx = blockIdx.x;
    const int dq = bx & 7, seg = (bx >> 3) & 7, h = (bx >> 6) & 7, b = bx >> 9;
    const int tid = threadIdx.x;
    const int q  = tid & 3;
    const int dl = tid >> 2;
    const int c0 = h * HEAD_DIM + dq * 32;

    float hs[16];
#pragma unroll
    for (int n = 0; n < 16; n++) hs[n] = 0.f;

    __shared__ float sB[2][8][64];
    __shared__ float sx[2][8][32];
    __shared__ float sa[2][8];

    const size_t rb = (size_t)b * SEQ + seg * SEG_LEN;
    const int st = tid >> 4, q4 = tid & 15;

    auto load_group = [&](int g, int bb) {
        const int t0 = g * 8;
        {   // B: 64 floats/step = 16 float4; 8 steps x 16 threads = 1 each
            const float* p = g_zx + (rb + t0 + st) * D_IN_PROJ + 2 * D_INNER + N_HEADS;
            reinterpret_cast<float4*>(&sB[bb][st][0])[q4] =
                reinterpret_cast<const float4*>(p)[q4];
        }
        {   // x: 32 floats/step; 16 threads x float2 each
            int i2 = q4 * 2;
            *reinterpret_cast<float2*>(&sx[bb][st][i2]) =
                *reinterpret_cast<const float2*>(&g_xconv[(rb + t0 + st) * D_INNER + c0 + i2]);
        }
        if (tid < 8) sa[bb][tid] = g_abar[(rb + t0 + tid) * N_HEADS + h];
    };

    load_group(0, 0);
    __syncthreads();

    for (int g = 0; g < SEG_LEN / 8; g++) {
        const int bb = g & 1;
        if (g + 1 < SEG_LEN / 8) load_group(g + 1, bb ^ 1);
#pragma unroll
        for (int s8 = 0; s8 < 8; s8++) {
            float a = sa[bb][s8];
            float x = sx[bb][s8][dl];
            const float4* Bv = reinterpret_cast<const float4*>(&sB[bb][s8][q * 16]);
#pragma unroll
            for (int i = 0; i < 4; i++) {
                float4 bq = Bv[i];
                hs[i*4+0] = fmaf(a, hs[i*4+0], bq.x * x);
                hs[i*4+1] = fmaf(a, hs[i*4+1], bq.y * x);
                hs[i*4+2] = fmaf(a, hs[i*4+2], bq.z * x);
                hs[i*4+3] = fmaf(a, hs[i*4+3], bq.w * x);
            }
        }
        __syncthreads();
    }

    size_t base = (((size_t)(b * 8 + h) * 8 + seg) * (HEAD_DIM * D_STATE))
                + (size_t)(dq * 32 + dl) * 64 + q * 16;
#pragma unroll
    for (int i = 0; i < 4; i++)
        *reinterpret_cast<float4*>(&g_state[base + i * 4]) =
            make_float4(hs[i*4+0], hs[i*4+1], hs[i*4+2], hs[i*4+3]);
}

// ---------------- scan pass C: inline combine + local scan + y + gate -------
__global__ __launch_bounds__(128) void scan_partC(const float* __restrict__ D_param)
{
    const int bx = blockIdx.x;
    const int dq = bx & 7, seg = (bx >> 3) & 7, h = (bx >> 6) & 7, b = bx >> 9;
    const int tid = threadIdx.x;
    const int q  = tid & 3;
    const int dl = tid >> 2;
    const int c0 = h * HEAD_DIM + dq * 32;
    const int c  = c0 + dl;
    const int bh = b * 8 + h;

    float hs[16];
#pragma unroll
    for (int n = 0; n < 16; n++) hs[n] = 0.f;
    if (seg > 0) {
        float f = 1.f;
        const size_t slice = (size_t)(dq * 32 + dl) * 64 + q * 16;
        for (int s = seg - 1; s >= 0; s--) {
            size_t base = ((size_t)bh * 8 + s) * (HEAD_DIM * D_STATE) + slice;
#pragma unroll
            for (int i = 0; i < 4; i++) {
                float4 v = *reinterpret_cast<const float4*>(&g_state[base + i * 4]);
                hs[i*4+0] = fmaf(f, v.x, hs[i*4+0]);
                hs[i*4+1] = fmaf(f, v.y, hs[i*4+1]);
                hs[i*4+2] = fmaf(f, v.z, hs[i*4+2]);
                hs[i*4+3] = fmaf(f, v.w, hs[i*4+3]);
            }
            f *= g_aseg[bh * 8 + s];
        }
    }

    __shared__ float sBC[2][8][128];
    __shared__ float sx[2][8][32];
    __shared__ float sz[2][8][32];
    __shared__ float sa[2][8];

    const float Dp = D_param[h];
    const size_t rb = (size_t)b * SEQ + seg * SEG_LEN;
    const int st = tid >> 4, q4 = tid & 15;

    auto load_group = [&](int g, int bb) {
        const int t0 = g * 8;
        {   // B|C: 128 floats/step = 32 float4; 16 threads x 2 float4 each
            const float* p = g_zx + (rb + t0 + st) * D_IN_PROJ + 2 * D_INNER + N_HEADS;
            reinterpret_cast<float4*>(&sBC[bb][st][0])[q4] =
                reinterpret_cast<const float4*>(p)[q4];
            reinterpret_cast<float4*>(&sBC[bb][st][0])[q4 + 16] =
                reinterpret_cast<const float4*>(p)[q4 + 16];
        }
        {   int i2 = q4 * 2;
            *reinterpret_cast<float2*>(&sx[bb][st][i2]) =
                *reinterpret_cast<const float2*>(&g_xconv[(rb + t0 + st) * D_INNER + c0 + i2]);
            *reinterpret_cast<float2*>(&sz[bb][st][i2]) =
                *reinterpret_cast<const float2*>(&g_zx[(rb + t0 + st) * D_IN_PROJ + c0 + i2]);
        }
        if (tid < 8) sa[bb][tid] = g_abar[(rb + t0 + tid) * N_HEADS + h];
    };

    load_group(0, 0);
    __syncthreads();

    for (int g = 0; g < SEG_LEN / 8; g++) {
        const int bb = g & 1;
        if (g + 1 < SEG_LEN / 8) load_group(g + 1, bb ^ 1);
#pragma unroll
        for (int s8 = 0; s8 < 8; s8++) {
            float a = sa[bb][s8];
            float x = sx[bb][s8][dl];
            const float4* Bv = reinterpret_cast<const float4*>(&sBC[bb][s8][q * 16]);
            const float4* Cv = reinterpret_cast<const float4*>(&sBC[bb][s8][64 + q * 16]);
            float y = 0.f;
#pragma unroll
            for (int i = 0; i < 4; i++) {
                float4 bq = Bv[i], cq = Cv[i];
                hs[i*4+0] = fmaf(a, hs[i*4+0], bq.x * x); y = fmaf(hs[i*4+0], cq.x, y);
                hs[i*4+1] = fmaf(a, hs[i*4+1], bq.y * x); y = fmaf(hs[i*4+1], cq.y, y);
                hs[i*4+2] = fmaf(a, hs[i*4+2], bq.z * x); y = fmaf(hs[i*4+2], cq.z, y);
                hs[i*4+3] = fmaf(a, hs[i*4+3], bq.w * x); y = fmaf(hs[i*4+3], cq.w, y);
            }
            y += __shfl_xor_sync(0xFFFFFFFFu, y, 1);
            y += __shfl_xor_sync(0xFFFFFFFFu, y, 2);
            if (q == 0) {
                float zv = sz[bb][s8][dl];
                float gate = zv / (1.f + expf(-zv));
                g_y[(rb + g * 8 + s8) * D_INNER + c] = (y + Dp * x) * gate;
            }
        }
        __syncthreads();
    }
}

// ---------------- rmsnorm + bf16 hi/lo split fused ---------------------------
__global__ __launch_bounds__(256) void rmsnorm_split_kernel(const float* __restrict__ norm_w)
{
    const int row = blockIdx.x;
    const float* y = g_y + (size_t)row * D_INNER;
    float4 v[2];
    float s = 0.f;
#pragma unroll
    for (int it = 0; it < 2; it++) {
        v[it] = reinterpret_cast<const float4*>(y)[threadIdx.x + it * 256];
        s = fmaf(v[it].x, v[it].x, s);
        s = fmaf(v[it].y, v[it].y, s);
        s = fmaf(v[it].z, v[it].z, s);
        s = fmaf(v[it].w, v[it].w, s);
    }
#pragma unroll
    for (int o = 16; o; o >>= 1) s += __shfl_xor_sync(0xFFFFFFFFu, s, o);
    __shared__ float red[8];
    if ((threadIdx.x & 31) == 0) red[threadIdx.x >> 5] = s;
    __syncthreads();
    if (threadIdx.x < 8) {
        s = red[threadIdx.x];
#pragma unroll
        for (int o = 4; o; o >>= 1) s += __shfl_xor_sync(0xFFu, s, o);
        if (threadIdx.x == 0) red[0] = s;
    }
    __syncthreads();
    const float scale = rsqrtf(red[0] * (1.f / D_INNER) + 1e-6f);

    __nv_bfloat16* hi = g_yhi + (size_t)row * D_INNER;
    __nv_bfloat16* lo = g_ylo + (size_t)row * D_INNER;
#pragma unroll
    for (int it = 0; it < 2; it++) {
        int i4 = threadIdx.x + it * 256;
        float4 w = reinterpret_cast<const float4*>(norm_w)[i4];
        float f0 = v[it].x * scale * w.x;
        float f1 = v[it].y * scale * w.y;
        float f2 = v[it].z * scale * w.z;
        float f3 = v[it].w * scale * w.w;
        __nv_bfloat16 h0 = __float2bfloat16(f0);
        __nv_bfloat16 h1 = __float2bfloat16(f1);
        __nv_bfloat16 h2 = __float2bfloat16(f2);
        __nv_bfloat16 h3 = __float2bfloat16(f3);
        __nv_bfloat16 l0 = __float2bfloat16(f0 - __bfloat162float(h0));
        __nv_bfloat16 l1 = __float2bfloat16(f1 - __bfloat162float(h1));
        __nv_bfloat16 l2 = __float2bfloat16(f2 - __bfloat162float(h2));
        __nv_bfloat16 l3 = __float2bfloat16(f3 - __bfloat162float(h3));
        __nv_bfloat162 hh0{h0, h1}, hh1{h2, h3}, ll0{l0, l1}, ll1{l2, l3};
        reinterpret_cast<__nv_bfloat162*>(hi)[i4 * 2 + 0] = hh0;
        reinterpret_cast<__nv_bfloat162*>(hi)[i4 * 2 + 1] = hh1;
        reinterpret_cast<__nv_bfloat162*>(lo)[i4 * 2 + 0] = ll0;
        reinterpret_cast<__nv_bfloat162*>(lo)[i4 * 2 + 1] = ll1;
    }
}

// ---------------- launch ----------------------------------------------------
extern "C" void kernel_launch(void* const* d_in, const int* in_sizes, int n_in,
                              void* d_out, int out_size)
{
    const float* x          = (const float*)d_in[0];
    const float* in_proj_w  = (const float*)d_in[1];
    const float* conv_w     = (const float*)d_in[2];
    const float* conv_b     = (const float*)d_in[3];
    const float* A_log      = (const float*)d_in[4];
    const float* D_param    = (const float*)d_in[5];
    const float* dt_bias    = (const float*)d_in[6];
    const float* norm_w     = (const float*)d_in[7];
    const float* out_proj_w = (const float*)d_in[8];
    float* out = (float*)d_out;

    float *p_zx;
    __nv_bfloat16 *p_xhi, *p_xlo, *p_w1hi, *p_w1lo, *p_yhi, *p_ylo, *p_w2hi, *p_w2lo;
    cudaGetSymbolAddress((void**)&p_zx,   g_zx);
    cudaGetSymbolAddress((void**)&p_xhi,  g_xhi);
    cudaGetSymbolAddress((void**)&p_xlo,  g_xlo);
    cudaGetSymbolAddress((void**)&p_w1hi, g_w1hi);
    cudaGetSymbolAddress((void**)&p_w1lo, g_w1lo);
    cudaGetSymbolAddress((void**)&p_yhi,  g_yhi);
    cudaGetSymbolAddress((void**)&p_ylo,  g_ylo);
    cudaGetSymbolAddress((void**)&p_w2hi, g_w2hi);
    cudaGetSymbolAddress((void**)&p_w2lo, g_w2lo);

    const int dyn_smem = 12 * TSZ;   // 192KB (3 stages)
    cudaFuncSetAttribute(gemm_mma, cudaFuncAttributeMaxDynamicSharedMemorySize, dyn_smem);

    // 0. split all fp32 inputs to bf16 hi/lo (one launch)
    {
        int total = N4X + N4W1 + N4W2;
        split_all<<<(total + 255) / 256, 256>>>(x, in_proj_w, out_proj_w);
    }
    // 1. in_proj
    {
        dim3 grid((D_IN_PROJ + 127) / 128, ML / 128);
        gemm_mma<<<grid, 256, dyn_smem>>>(p_xhi, p_xlo, p_w1hi, p_w1lo,
                                          p_zx, ML, D_IN_PROJ, DIMM);
    }
    // 2. abar + aseg (needs only g_zx)
    abar_aseg_kernel<<<16, 256>>>(A_log, dt_bias);
    // 3. conv + silu
    conv_silu_kernel<<<(ML * D_INNER) / 256, 256>>>(conv_w, conv_b);
    // 4. two-level scan (combine inlined into pass C)
    scan_partA<<<1024, 128>>>();
    scan_partC<<<1024, 128>>>(D_param);
    // 5. rmsnorm + y split fused
    rmsnorm_split_kernel<<<ML, 256>>>(norm_w);
    // 6. out_proj
    {
        dim3 grid(DIMM / 128, ML / 128);
        gemm_mma<<<grid, 256, dyn_smem>>>(p_yhi, p_ylo, p_w2hi, p_w2lo,
                                          out, ML, DIMM, D_INNER);
    }
}

// round 14
// speedup vs baseline: 1.0639x; 1.0054x over previous
#include <cuda_runtime.h>
#include <cuda_bf16.h>
#include <math.h>
#include <stdint.h>

#define BATCH    2
#define SEQ      1024
#define DIMM     1024
#define D_STATE  64
#define D_CONV   4
#define N_HEADS  8
#define D_INNER  2048
#define HEAD_DIM 256
#define D_IN_PROJ 4232          // 2048 + 2048 + 8 + 64 + 64
#define ML       (BATCH*SEQ)    // 2048
#define NSEG     8
#define SEG_LEN  128            // SEQ / NSEG

// ---------------- scratch (device globals: allocation-free) ----------------
__device__ float g_zx[(size_t)ML * D_IN_PROJ];      // in_proj output
__device__ float g_xconv[(size_t)ML * D_INNER];     // silu(conv(xc)) == xh
__device__ float g_y[(size_t)ML * D_INNER];         // (y+Dx)*silu(z)
__device__ float g_abar[ML * N_HEADS];
__device__ float g_aseg[BATCH * N_HEADS * NSEG];    // per-segment decay product
__device__ float g_state[(size_t)BATCH * N_HEADS * NSEG * HEAD_DIM * D_STATE]; // 8MB

// bf16 hi/lo split buffers
__device__ __nv_bfloat16 g_xhi[(size_t)ML * DIMM];
__device__ __nv_bfloat16 g_xlo[(size_t)ML * DIMM];
__device__ __nv_bfloat16 g_w1hi[(size_t)D_IN_PROJ * DIMM];
__device__ __nv_bfloat16 g_w1lo[(size_t)D_IN_PROJ * DIMM];
__device__ __nv_bfloat16 g_yhi[(size_t)ML * D_INNER];
__device__ __nv_bfloat16 g_ylo[(size_t)ML * D_INNER];
__device__ __nv_bfloat16 g_w2hi[(size_t)DIMM * D_INNER];
__device__ __nv_bfloat16 g_w2lo[(size_t)DIMM * D_INNER];

// ---------------- PTX helpers ------------------------------------------------
__device__ __forceinline__ uint32_t smem_u32(const void* p) {
    uint32_t a;
    asm("{ .reg .u64 t; cvta.to.shared.u64 t, %1; cvt.u32.u64 %0, t; }"
        : "=r"(a) : "l"(p));
    return a;
}
__device__ __forceinline__ void cp_async16(uint32_t saddr, const void* gaddr, uint32_t srcsz) {
    asm volatile("cp.async.cg.shared.global [%0], [%1], 16, %2;"
                 :: "r"(saddr), "l"(gaddr), "r"(srcsz) : "memory");
}
__device__ __forceinline__ void cp_commit() {
    asm volatile("cp.async.commit_group;" ::: "memory");
}
__device__ __forceinline__ void cp_wait1() {
    asm volatile("cp.async.wait_group 1;" ::: "memory");
}
__device__ __forceinline__ void ldsm_x4(uint32_t* r, uint32_t addr) {
    asm volatile("ldmatrix.sync.aligned.m8n8.x4.shared.b16 {%0,%1,%2,%3}, [%4];"
                 : "=r"(r[0]), "=r"(r[1]), "=r"(r[2]), "=r"(r[3]) : "r"(addr));
}
__device__ __forceinline__ void mma16816(float* c, const uint32_t* a, const uint32_t* b) {
    asm volatile(
        "mma.sync.aligned.m16n8k16.row.col.f32.bf16.bf16.f32 "
        "{%0,%1,%2,%3}, {%4,%5,%6,%7}, {%8,%9}, {%0,%1,%2,%3};"
        : "+f"(c[0]), "+f"(c[1]), "+f"(c[2]), "+f"(c[3])
        : "r"(a[0]), "r"(a[1]), "r"(a[2]), "r"(a[3]), "r"(b[0]), "r"(b[1]));
}
// packed f32x2 (Blackwell base-family PTX)
__device__ __forceinline__ uint64_t pk2(float lo, float hi) {
    uint64_t r; asm("mov.b64 %0, {%1, %2};" : "=l"(r) : "f"(lo), "f"(hi)); return r;
}
__device__ __forceinline__ void upk2(uint64_t v, float& lo, float& hi) {
    asm("mov.b64 {%0, %1}, %2;" : "=f"(lo), "=f"(hi) : "l"(v));
}
__device__ __forceinline__ uint64_t mul2(uint64_t a, uint64_t b) {
    uint64_t r; asm("mul.rn.f32x2 %0, %1, %2;" : "=l"(r) : "l"(a), "l"(b)); return r;
}
__device__ __forceinline__ uint64_t fma2(uint64_t a, uint64_t b, uint64_t c) {
    uint64_t r; asm("fma.rn.f32x2 %0, %1, %2, %3;" : "=l"(r) : "l"(a), "l"(b), "l"(c)); return r;
}

// ---------------- fused fp32 -> bf16 hi/lo split for x, w1, w2 --------------
#define N4X  (ML * DIMM / 4)            // 524288
#define N4W1 (D_IN_PROJ * DIMM / 4)     // 1083392
#define N4W2 (DIMM * D_INNER / 4)       // 524288
__global__ __launch_bounds__(256) void split_all(
    const float* __restrict__ x, const float* __restrict__ w1,
    const float* __restrict__ w2)
{
    int i = blockIdx.x * 256 + threadIdx.x;
    const float* s;
    __nv_bfloat16 *hi, *lo;
    int j;
    if (i < N4X) { s = x; hi = g_xhi; lo = g_xlo; j = i; }
    else if (i < N4X + N4W1) { s = w1; hi = g_w1hi; lo = g_w1lo; j = i - N4X; }
    else if (i < N4X + N4W1 + N4W2) { s = w2; hi = g_w2hi; lo = g_w2lo; j = i - N4X - N4W1; }
    else return;

    float4 v = reinterpret_cast<const float4*>(s)[j];
    __nv_bfloat16 h0 = __float2bfloat16(v.x);
    __nv_bfloat16 h1 = __float2bfloat16(v.y);
    __nv_bfloat16 h2 = __float2bfloat16(v.z);
    __nv_bfloat16 h3 = __float2bfloat16(v.w);
    __nv_bfloat16 l0 = __float2bfloat16(v.x - __bfloat162float(h0));
    __nv_bfloat16 l1 = __float2bfloat16(v.y - __bfloat162float(h1));
    __nv_bfloat16 l2 = __float2bfloat16(v.z - __bfloat162float(h2));
    __nv_bfloat16 l3 = __float2bfloat16(v.w - __bfloat162float(h3));
    __nv_bfloat162 hh0{h0, h1}, hh1{h2, h3}, ll0{l0, l1}, ll1{l2, l3};
    reinterpret_cast<__nv_bfloat162*>(hi)[j * 2 + 0] = hh0;
    reinterpret_cast<__nv_bfloat162*>(hi)[j * 2 + 1] = hh1;
    reinterpret_cast<__nv_bfloat162*>(lo)[j * 2 + 0] = ll0;
    reinterpret_cast<__nv_bfloat162*>(lo)[j * 2 + 1] = ll1;
}

// ---------------- mma.sync GEMM (bf16x3, 3-stage, 1 barrier/chunk) ----------
#define TSZ 16384
__global__ __launch_bounds__(256, 1) void gemm_mma(
    const __nv_bfloat16* __restrict__ Ahi, const __nv_bfloat16* __restrict__ Alo,
    const __nv_bfloat16* __restrict__ Bhi, const __nv_bfloat16* __restrict__ Blo,
    float* __restrict__ C, int M, int N, int K)
{
    extern __shared__ char smem[];
    const int tid  = threadIdx.x;
    const int wid  = tid >> 5;
    const int lane = tid & 31;
    const int bm = blockIdx.y * 128, bn = blockIdx.x * 128;
    const int wm = (wid >> 2) * 64;
    const int wn = (wid & 3) * 32;

    const uint32_t sbase = smem_u32(smem);

    float acc[4][4][4];
#pragma unroll
    for (int mi = 0; mi < 4; mi++)
#pragma unroll
        for (int ni = 0; ni < 4; ni++)
#pragma unroll
            for (int v = 0; v < 4; v++) acc[mi][ni][v] = 0.f;

    const int NC = K >> 6;

    auto load_stage = [&](int buf, int k0) {
        uint32_t st = sbase + buf * 4 * TSZ;
#pragma unroll
        for (int it = 0; it < 4; it++) {
            int cid = it * 256 + tid;
            int r = cid >> 3, j = cid & 7;
            uint32_t swz = (uint32_t)((r * 8 + (j ^ (r & 7))) * 16);
            size_t aoff = (size_t)(bm + r) * K + k0 + j * 8;
            cp_async16(st + swz,           Ahi + aoff, 16);
            cp_async16(st + TSZ + swz,     Alo + aoff, 16);
            int n = bn + r;
            uint32_t ok = (n < N) ? 16u : 0u;
            size_t boff = (size_t)(ok ? n : 0) * K + k0 + j * 8;
            cp_async16(st + 2 * TSZ + swz, Bhi + boff, ok);
            cp_async16(st + 3 * TSZ + swz, Blo + boff, ok);
        }
    };

    load_stage(0, 0);  cp_commit();
    load_stage(1, 64); cp_commit();

    const int rA = wm + (lane & 15);
    const int jA = lane >> 4;
    const int qB = lane >> 3;
    const int rB = wn + ((qB >= 2) ? 8 : 0) + (lane & 7);
    const int jB = qB & 1;

    int buf = 0;
    for (int ch = 0; ch < NC; ch++) {
        cp_wait1();
        __syncthreads();
        if (ch + 2 < NC) load_stage((buf + 2 >= 3) ? buf - 1 : buf + 2, (ch + 2) << 6);
        cp_commit();

        uint32_t stA  = sbase + buf * 4 * TSZ;
        uint32_t stAl = stA + TSZ;
        uint32_t stB  = stA + 2 * TSZ;
        uint32_t stBl = stA + 3 * TSZ;

#pragma unroll
        for (int ks = 0; ks < 4; ks++) {
            uint32_t bh[2][4], bl[2][4];
#pragma unroll
            for (int np = 0; np < 2; np++) {
                int r = rB + np * 16;
                int jj = 2 * ks + jB;
                uint32_t off = (uint32_t)((r * 8 + (jj ^ (r & 7))) * 16);
                ldsm_x4(bh[np], stB  + off);
                ldsm_x4(bl[np], stBl + off);
            }
#pragma unroll
            for (int mi = 0; mi < 4; mi++) {
                uint32_t ah[4], al[4];
                int r = rA + mi * 16;
                int jj = 2 * ks + jA;
                uint32_t off = (uint32_t)((r * 8 + (jj ^ (r & 7))) * 16);
                ldsm_x4(ah, stA  + off);
                ldsm_x4(al, stAl + off);
#pragma unroll
                for (int ni = 0; ni < 4; ni++)
                    mma16816(acc[mi][ni], ah, &bh[ni >> 1][(ni & 1) * 2]);
#pragma unroll
                for (int ni = 0; ni < 4; ni++)
                    mma16816(acc[mi][ni], ah, &bl[ni >> 1][(ni & 1) * 2]);
#pragma unroll
                for (int ni = 0; ni < 4; ni++)
                    mma16816(acc[mi][ni], al, &bh[ni >> 1][(ni & 1) * 2]);
            }
        }
        buf = (buf + 1 >= 3) ? 0 : buf + 1;
    }

    const int gid = lane >> 2, tig = lane & 3;
#pragma unroll
    for (int mi = 0; mi < 4; mi++) {
        int row = bm + wm + mi * 16 + gid;
#pragma unroll
        for (int ni = 0; ni < 4; ni++) {
            int col = bn + wn + ni * 8 + tig * 2;
            if (col < N) {
                float2 lo2 = make_float2(acc[mi][ni][0], acc[mi][ni][1]);
                float2 hi2 = make_float2(acc[mi][ni][2], acc[mi][ni][3]);
                *reinterpret_cast<float2*>(C + (size_t)row * N + col) = lo2;
                *reinterpret_cast<float2*>(C + (size_t)(row + 8) * N + col) = hi2;
            }
        }
    }
}

// ---------------- conv(4) + silu, 4 timesteps per thread --------------------
// idx over ML/4 * D_INNER; each thread loads 7 rows, emits 4 outputs.
__global__ __launch_bounds__(256) void conv_silu_kernel(
    const float* __restrict__ conv_w, const float* __restrict__ conv_b)
{
    int idx = blockIdx.x * 256 + threadIdx.x;
    int c  = idx & (D_INNER - 1);
    int mq = idx >> 11;                  // 0 .. ML/4-1
    int l0 = (mq & (SEQ / 4 - 1)) * 4;
    int b  = mq >> 8;                    // mq / (SEQ/4)

    float u[7];
#pragma unroll
    for (int k = 0; k < 7; k++) {
        int ls = l0 + k - 3;
        u[k] = (ls >= 0)
            ? g_zx[(size_t)(b * SEQ + ls) * D_IN_PROJ + D_INNER + c] : 0.f;
    }
    float w0 = conv_w[c * 4 + 0], w1 = conv_w[c * 4 + 1];
    float w2 = conv_w[c * 4 + 2], w3 = conv_w[c * 4 + 3];
    float cb = conv_b[c];
#pragma unroll
    for (int t = 0; t < 4; t++) {
        float acc = cb;
        acc = fmaf(u[t + 0], w0, acc);
        acc = fmaf(u[t + 1], w1, acc);
        acc = fmaf(u[t + 2], w2, acc);
        acc = fmaf(u[t + 3], w3, acc);
        acc = acc / (1.f + expf(-acc));
        g_xconv[(size_t)(b * SEQ + l0 + t) * D_INNER + c] = acc;
    }
}

// ---------------- abar + per-segment decay product (1 warp per (b,h,seg)) ---
__global__ __launch_bounds__(256) void abar_aseg_kernel(
    const float* __restrict__ A_log, const float* __restrict__ dt_bias)
{
    int w = blockIdx.x * 8 + (threadIdx.x >> 5);    // 0..127
    int lane = threadIdx.x & 31;
    int seg = w & 7;
    int h   = (w >> 3) & 7;
    int b   = w >> 6;
    int t0  = seg * SEG_LEN;
    const float negA = -expf(A_log[h]);
    const float db   = dt_bias[h];
    float p = 1.f;
#pragma unroll
    for (int k = 0; k < 4; k++) {
        int t = t0 + lane * 4 + k;
        float raw = g_zx[(size_t)(b * SEQ + t) * D_IN_PROJ + 2 * D_INNER + h] + db;
        float sp  = (raw > 20.f) ? raw : log1pf(expf(raw));
        float a   = expf(negA * sp);
        g_abar[(b * SEQ + t) * N_HEADS + h] = a;
        p *= a;
    }
#pragma unroll
    for (int o = 16; o; o >>= 1)
        p *= __shfl_xor_sync(0xFFFFFFFFu, p, o);
    if (lane == 0) g_aseg[w] = p;
}

// ---------------- scan pass A (f32x2 packed states) --------------------------
__global__ __launch_bounds__(128) void scan_partA()
{
    const int bx = blockIdx.x;
    const int dq = bx & 7, seg = (bx >> 3) & 7, h = (bx >> 6) & 7, b = bx >> 9;
    const int tid = threadIdx.x;
    const int q  = tid & 3;
    const int dl = tid >> 2;
    const int c0 = h * HEAD_DIM + dq * 32;

    uint64_t hs2[8];
#pragma unroll
    for (int n = 0; n < 8; n++) hs2[n] = 0ull;

    __shared__ __align__(16) float sB[2][8][64];
    __shared__ float sx[2][8][32];
    __shared__ float sa[2][8];

    const size_t rb = (size_t)b * SEQ + seg * SEG_LEN;
    const int st = tid >> 4, q4 = tid & 15;

    auto load_group = [&](int g, int bb) {
        const int t0 = g * 8;
        {   const float* p = g_zx + (rb + t0 + st) * D_IN_PROJ + 2 * D_INNER + N_HEADS;
            reinterpret_cast<float4*>(&sB[bb][st][0])[q4] =
                reinterpret_cast<const float4*>(p)[q4]; }
        {   int i2 = q4 * 2;
            *reinterpret_cast<float2*>(&sx[bb][st][i2]) =
                *reinterpret_cast<const float2*>(&g_xconv[(rb + t0 + st) * D_INNER + c0 + i2]); }
        if (tid < 8) sa[bb][tid] = g_abar[(rb + t0 + tid) * N_HEADS + h];
    };

    load_group(0, 0);
    __syncthreads();

    for (int g = 0; g < SEG_LEN / 8; g++) {
        const int bb = g & 1;
        if (g + 1 < SEG_LEN / 8) load_group(g + 1, bb ^ 1);
#pragma unroll
        for (int s8 = 0; s8 < 8; s8++) {
            float a = sa[bb][s8];
            float x = sx[bb][s8][dl];
            uint64_t a2 = pk2(a, a), x2 = pk2(x, x);
            const uint64_t* B2 = reinterpret_cast<const uint64_t*>(&sB[bb][s8][q * 16]);
#pragma unroll
            for (int i = 0; i < 8; i++)
                hs2[i] = fma2(a2, hs2[i], mul2(B2[i], x2));
        }
        __syncthreads();
    }

    size_t base = (((size_t)(b * 8 + h) * 8 + seg) * (HEAD_DIM * D_STATE))
                + (size_t)(dq * 32 + dl) * 64 + q * 16;
    uint64_t* out = reinterpret_cast<uint64_t*>(&g_state[base]);
#pragma unroll
    for (int i = 0; i < 8; i++) out[i] = hs2[i];
}

// ---------------- scan pass C (f32x2 packed; combine + scan + y + gate) -----
__global__ __launch_bounds__(128) void scan_partC(const float* __restrict__ D_param)
{
    const int bx = blockIdx.x;
    const int dq = bx & 7, seg = (bx >> 3) & 7, h = (bx >> 6) & 7, b = bx >> 9;
    const int tid = threadIdx.x;
    const int q  = tid & 3;
    const int dl = tid >> 2;
    const int c0 = h * HEAD_DIM + dq * 32;
    const int c  = c0 + dl;
    const int bh = b * 8 + h;

    uint64_t hs2[8];
#pragma unroll
    for (int n = 0; n < 8; n++) hs2[n] = 0ull;
    if (seg > 0) {
        float f = 1.f;
        const size_t slice = (size_t)(dq * 32 + dl) * 64 + q * 16;
        for (int s = seg - 1; s >= 0; s--) {
            const uint64_t* v2 = reinterpret_cast<const uint64_t*>(
                &g_state[((size_t)bh * 8 + s) * (HEAD_DIM * D_STATE) + slice]);
            uint64_t f2 = pk2(f, f);
#pragma unroll
            for (int i = 0; i < 8; i++)
                hs2[i] = fma2(f2, v2[i], hs2[i]);
            f *= g_aseg[bh * 8 + s];
        }
    }

    __shared__ __align__(16) float sBC[2][8][128];
    __shared__ float sx[2][8][32];
    __shared__ float sz[2][8][32];
    __shared__ float sa[2][8];

    const float Dp = D_param[h];
    const size_t rb = (size_t)b * SEQ + seg * SEG_LEN;
    const int st = tid >> 4, q4 = tid & 15;

    auto load_group = [&](int g, int bb) {
        const int t0 = g * 8;
        {   const float* p = g_zx + (rb + t0 + st) * D_IN_PROJ + 2 * D_INNER + N_HEADS;
            reinterpret_cast<float4*>(&sBC[bb][st][0])[q4] =
                reinterpret_cast<const float4*>(p)[q4];
            reinterpret_cast<float4*>(&sBC[bb][st][0])[q4 + 16] =
                reinterpret_cast<const float4*>(p)[q4 + 16]; }
        {   int i2 = q4 * 2;
            *reinterpret_cast<float2*>(&sx[bb][st][i2]) =
                *reinterpret_cast<const float2*>(&g_xconv[(rb + t0 + st) * D_INNER + c0 + i2]);
            *reinterpret_cast<float2*>(&sz[bb][st][i2]) =
                *reinterpret_cast<const float2*>(&g_zx[(rb + t0 + st) * D_IN_PROJ + c0 + i2]); }
        if (tid < 8) sa[bb][tid] = g_abar[(rb + t0 + tid) * N_HEADS + h];
    };

    load_group(0, 0);
    __syncthreads();

    for (int g = 0; g < SEG_LEN / 8; g++) {
        const int bb = g & 1;
        if (g + 1 < SEG_LEN / 8) load_group(g + 1, bb ^ 1);
#pragma unroll
        for (int s8 = 0; s8 < 8; s8++) {
            float a = sa[bb][s8];
            float x = sx[bb][s8][dl];
            uint64_t a2 = pk2(a, a), x2 = pk2(x, x);
            const uint64_t* B2 = reinterpret_cast<const uint64_t*>(&sBC[bb][s8][q * 16]);
            const uint64_t* C2 = reinterpret_cast<const uint64_t*>(&sBC[bb][s8][64 + q * 16]);
            uint64_t y2 = 0ull;
#pragma unroll
            for (int i = 0; i < 8; i++) {
                hs2[i] = fma2(a2, hs2[i], mul2(B2[i], x2));
                y2 = fma2(hs2[i], C2[i], y2);
            }
            float ylo, yhi;
            upk2(y2, ylo, yhi);
            float y = ylo + yhi;
            y += __shfl_xor_sync(0xFFFFFFFFu, y, 1);
            y += __shfl_xor_sync(0xFFFFFFFFu, y, 2);
            if (q == 0) {
                float zv = sz[bb][s8][dl];
                float gate = zv / (1.f + expf(-zv));
                g_y[(rb + g * 8 + s8) * D_INNER + c] = (y + Dp * x) * gate;
            }
        }
        __syncthreads();
    }
}

// ---------------- rmsnorm + bf16 hi/lo split fused ---------------------------
__global__ __launch_bounds__(256) void rmsnorm_split_kernel(const float* __restrict__ norm_w)
{
    const int row = blockIdx.x;
    const float* y = g_y + (size_t)row * D_INNER;
    float4 v[2];
    float s = 0.f;
#pragma unroll
    for (int it = 0; it < 2; it++) {
        v[it] = reinterpret_cast<const float4*>(y)[threadIdx.x + it * 256];
        s = fmaf(v[it].x, v[it].x, s);
        s = fmaf(v[it].y, v[it].y, s);
        s = fmaf(v[it].z, v[it].z, s);
        s = fmaf(v[it].w, v[it].w, s);
    }
#pragma unroll
    for (int o = 16; o; o >>= 1) s += __shfl_xor_sync(0xFFFFFFFFu, s, o);
    __shared__ float red[8];
    if ((threadIdx.x & 31) == 0) red[threadIdx.x >> 5] = s;
    __syncthreads();
    if (threadIdx.x < 8) {
        s = red[threadIdx.x];
#pragma unroll
        for (int o = 4; o; o >>= 1) s += __shfl_xor_sync(0xFFu, s, o);
        if (threadIdx.x == 0) red[0] = s;
    }
    __syncthreads();
    const float scale = rsqrtf(red[0] * (1.f / D_INNER) + 1e-6f);

    __nv_bfloat16* hi = g_yhi + (size_t)row * D_INNER;
    __nv_bfloat16* lo = g_ylo + (size_t)row * D_INNER;
#pragma unroll
    for (int it = 0; it < 2; it++) {
        int i4 = threadIdx.x + it * 256;
        float4 w = reinterpret_cast<const float4*>(norm_w)[i4];
        float f0 = v[it].x * scale * w.x;
        float f1 = v[it].y * scale * w.y;
        float f2 = v[it].z * scale * w.z;
        float f3 = v[it].w * scale * w.w;
        __nv_bfloat16 h0 = __float2bfloat16(f0);
        __nv_bfloat16 h1 = __float2bfloat16(f1);
        __nv_bfloat16 h2 = __float2bfloat16(f2);
        __nv_bfloat16 h3 = __float2bfloat16(f3);
        __nv_bfloat16 l0 = __float2bfloat16(f0 - __bfloat162float(h0));
        __nv_bfloat16 l1 = __float2bfloat16(f1 - __bfloat162float(h1));
        __nv_bfloat16 l2 = __float2bfloat16(f2 - __bfloat162float(h2));
        __nv_bfloat16 l3 = __float2bfloat16(f3 - __bfloat162float(h3));
        __nv_bfloat162 hh0{h0, h1}, hh1{h2, h3}, ll0{l0, l1}, ll1{l2, l3};
        reinterpret_cast<__nv_bfloat162*>(hi)[i4 * 2 + 0] = hh0;
        reinterpret_cast<__nv_bfloat162*>(hi)[i4 * 2 + 1] = hh1;
        reinterpret_cast<__nv_bfloat162*>(lo)[i4 * 2 + 0] = ll0;
        reinterpret_cast<__nv_bfloat162*>(lo)[i4 * 2 + 1] = ll1;
    }
}

// ---------------- launch ----------------------------------------------------
extern "C" void kernel_launch(void* const* d_in, const int* in_sizes, int n_in,
                              void* d_out, int out_size)
{
    const float* x          = (const float*)d_in[0];
    const float* in_proj_w  = (const float*)d_in[1];
    const float* conv_w     = (const float*)d_in[2];
    const float* conv_b     = (const float*)d_in[3];
    const float* A_log      = (const float*)d_in[4];
    const float* D_param    = (const float*)d_in[5];
    const float* dt_bias    = (const float*)d_in[6];
    const float* norm_w     = (const float*)d_in[7];
    const float* out_proj_w = (const float*)d_in[8];
    float* out = (float*)d_out;

    float *p_zx;
    __nv_bfloat16 *p_xhi, *p_xlo, *p_w1hi, *p_w1lo, *p_yhi, *p_ylo, *p_w2hi, *p_w2lo;
    cudaGetSymbolAddress((void**)&p_zx,   g_zx);
    cudaGetSymbolAddress((void**)&p_xhi,  g_xhi);
    cudaGetSymbolAddress((void**)&p_xlo,  g_xlo);
    cudaGetSymbolAddress((void**)&p_w1hi, g_w1hi);
    cudaGetSymbolAddress((void**)&p_w1lo, g_w1lo);
    cudaGetSymbolAddress((void**)&p_yhi,  g_yhi);
    cudaGetSymbolAddress((void**)&p_ylo,  g_ylo);
    cudaGetSymbolAddress((void**)&p_w2hi, g_w2hi);
    cudaGetSymbolAddress((void**)&p_w2lo, g_w2lo);

    const int dyn_smem = 12 * TSZ;   // 192KB (3 stages)
    cudaFuncSetAttribute(gemm_mma, cudaFuncAttributeMaxDynamicSharedMemorySize, dyn_smem);

    // 0. split all fp32 inputs to bf16 hi/lo (one launch)
    {
        int total = N4X + N4W1 + N4W2;
        split_all<<<(total + 255) / 256, 256>>>(x, in_proj_w, out_proj_w);
    }
    // 1. in_proj
    {
        dim3 grid((D_IN_PROJ + 127) / 128, ML / 128);
        gemm_mma<<<grid, 256, dyn_smem>>>(p_xhi, p_xlo, p_w1hi, p_w1lo,
                                          p_zx, ML, D_IN_PROJ, DIMM);
    }
    // 2. abar + aseg (needs only g_zx)
    abar_aseg_kernel<<<16, 256>>>(A_log, dt_bias);
    // 3. conv + silu (4 steps/thread)
    conv_silu_kernel<<<(ML / 4 * D_INNER) / 256, 256>>>(conv_w, conv_b);
    // 4. two-level scan (f32x2 packed)
    scan_partA<<<1024, 128>>>();
    scan_partC<<<1024, 128>>>(D_param);
    // 5. rmsnorm + y split fused
    rmsnorm_split_kernel<<<ML, 256>>>(norm_w);
    // 6. out_proj
    {
        dim3 grid(DIMM / 128, ML / 128);
        gemm_mma<<<grid, 256, dyn_smem>>>(p_yhi, p_ylo, p_w2hi, p_w2lo,
                                          out, ML, DIMM, D_INNER);
    }
}